// round 10
// baseline (speedup 1.0000x reference)
#include <cuda_runtime.h>
#include <cuda_bf16.h>
#include <math.h>

// ---------------------------------------------------------------------------
// DIM=3 Euclidean GA. 8 blades (order: (),e0,e1,e2,e01,e02,e12,e012),
// grades {0,1,1,1,2,2,2,3}. KERNEL_SIZE=7 -> 343 pts. C_IN=C_OUT=32, H=64,
// 4 layers, P=20 paths. Output (256,256,7,7,7) fp32 = 22,478,848 elems.
// ---------------------------------------------------------------------------
#define NP 2          // grid points per block in k_mlp
#define FACTOR_ 0.05399492471f   // 1/sqrt(343)

// -------- device scratch (no allocations allowed) --------
__device__ float g_gw[4 * 64 * 20 * 64];   // gps_w  -> [l][i][p][o]
__device__ float g_lw[3 * 64 * 4 * 64];    // lins_W -> [l][i][g][o]
__device__ float g_l0[33 * 4 * 64];        // lin0_W -> [i][g][o]
__device__ float g_ow[64 * 4 * 1024];      // out_W  -> [c][g][oi]
__device__ float g_kf[1024 * 8 * 344];     // kfield [oi][b][n] (n-stride 344)

__constant__ int c_mask[8] = {0, 1, 2, 4, 3, 5, 6, 7};
__constant__ int c_inv[8]  = {0, 1, 2, 4, 3, 5, 6, 7}; // mask -> blade idx
__constant__ int c_gr[8]   = {0, 1, 1, 1, 2, 2, 2, 3};

// -------- compile-time tables for the gp layers --------
struct Tables {
    int   pid[4][4][4];   // path id per (left grade, out grade, right grade)
    int   pairM[8][8];    // for (j,k): m with mask_k ^ mask_m == mask_j
    float pairSign[8][8]; // sign of blade_k * blade_m
    int   pairPid[8][8];  // pid[gr_k][gr_j][gr_m]
};

__host__ __device__ constexpr int popc_(int x) {
    return (x & 1) + ((x >> 1) & 1) + ((x >> 2) & 1);
}
__host__ __device__ constexpr int signOf_(int a, int b) {
    int s = 0;
    for (int i = 0; i < 3; i++)
        if (b & (1 << i)) s += popc_(a >> (i + 1));
    return (s & 1) ? -1 : 1;
}

__host__ __device__ constexpr Tables buildTables() {
    Tables T{};
    constexpr int MSK[8] = {0, 1, 2, 4, 3, 5, 6, 7};
    constexpr int GRD[8] = {0, 1, 1, 1, 2, 2, 2, 3};
    // PATHS: lexicographic (a,b,c) with b = a+c-2t feasible (matches np.argwhere)
    int p = 0;
    for (int a = 0; a < 4; a++)
        for (int b = 0; b < 4; b++)
            for (int c = 0; c < 4; c++) {
                bool v = false;
                for (int t = 0; t <= 3; t++)
                    if (t <= a && t <= c && a + c - t <= 3 && a + c - 2 * t == b) v = true;
                T.pid[a][b][c] = v ? p++ : -1;
            }
    for (int j = 0; j < 8; j++)
        for (int k = 0; k < 8; k++) {
            int mm = MSK[k] ^ MSK[j];
            int m = 0;
            for (int q = 0; q < 8; q++)
                if (MSK[q] == mm) m = q;
            T.pairM[j][k] = m;
            T.pairSign[j][k] = (float)signOf_(MSK[k], mm);
            T.pairPid[j][k] = T.pid[GRD[k]][GRD[j]][GRD[m]];
        }
    return T;
}

__device__ int pid_rt(int a, int b, int c) {
    int p = 0;
    for (int aa = 0; aa < 4; aa++)
        for (int bb = 0; bb < 4; bb++)
            for (int cc = 0; cc < 4; cc++) {
                bool v = false;
                for (int t = 0; t <= 3; t++)
                    if (t <= aa && t <= cc && aa + cc - t <= 3 && aa + cc - 2 * t == bb) v = true;
                if (aa == a && bb == b && cc == c) return v ? p : 0;
                if (v) p++;
            }
    return 0;
}

// ---------------------------------------------------------------------------
// prep: transpose weights so MLP loads are lane-coalesced (o last)
// ---------------------------------------------------------------------------
__global__ void k_prep(const float* __restrict__ gps_w, const float* __restrict__ lins_W,
                       const float* __restrict__ lin0_W, const float* __restrict__ out_W) {
    const int N1 = 327680, N2 = 49152, N3 = 8448, N4 = 262144;
    int idx = blockIdx.x * blockDim.x + threadIdx.x;
    if (idx < N1) {
        int o = idx & 63; int r = idx >> 6; int p = r % 20; r /= 20;
        int i = r & 63; int l = r >> 6;
        g_gw[idx] = gps_w[((l * 64 + o) * 64 + i) * 20 + p];
    } else if (idx < N1 + N2) {
        int j = idx - N1; int o = j & 63; int r = j >> 6; int g = r & 3; r >>= 2;
        int i = r & 63; int l = r >> 6;
        g_lw[j] = lins_W[((l * 4 + g) * 64 + o) * 64 + i];
    } else if (idx < N1 + N2 + N3) {
        int j = idx - N1 - N2; int o = j & 63; int r = j >> 6; int g = r & 3; int i = r >> 2;
        g_l0[j] = lin0_W[(g * 64 + o) * 33 + i];
    } else if (idx < N1 + N2 + N3 + N4) {
        int j = idx - N1 - N2 - N3; int oi = j & 1023; int r = j >> 10; int g = r & 3; int c = r >> 2;
        g_ow[j] = out_W[(g * 1024 + oi) * 64 + c];
    }
}

// ---------------------------------------------------------------------------
// fused MLP helpers (thread = (channel o, point p))
// ---------------------------------------------------------------------------
__device__ __forceinline__ void lin_silu(const float* __restrict__ lw, const float* __restrict__ bias,
                                         const float* __restrict__ aa, const float* __restrict__ ab,
                                         const float* __restrict__ xin, float* __restrict__ outp,
                                         int o, int NI) {
    float acc[8] = {0, 0, 0, 0, 0, 0, 0, 0};
    for (int i = 0; i < NI; i++) {
        float w0 = lw[(i * 4 + 0) * 64 + o];
        float w1 = lw[(i * 4 + 1) * 64 + o];
        float w2 = lw[(i * 4 + 2) * 64 + o];
        float w3 = lw[(i * 4 + 3) * 64 + o];
        const float* x8 = xin + i * 8;   // warp-broadcast smem loads
        acc[0] += w0 * x8[0];
        acc[1] += w1 * x8[1]; acc[2] += w1 * x8[2]; acc[3] += w1 * x8[3];
        acc[4] += w2 * x8[4]; acc[5] += w2 * x8[5]; acc[6] += w2 * x8[6];
        acc[7] += w3 * x8[7];
    }
    acc[0] += bias[o];
    float q0 = acc[0] * acc[0];
    float q1 = acc[1] * acc[1] + acc[2] * acc[2] + acc[3] * acc[3];
    float q2 = acc[4] * acc[4] + acc[5] * acc[5] + acc[6] * acc[6];
    float q3 = acc[7] * acc[7];
    float g0 = 1.0f / (1.0f + expf(-(aa[o * 4 + 0] * q0 + ab[o * 4 + 0])));
    float g1 = 1.0f / (1.0f + expf(-(aa[o * 4 + 1] * q1 + ab[o * 4 + 1])));
    float g2 = 1.0f / (1.0f + expf(-(aa[o * 4 + 2] * q2 + ab[o * 4 + 2])));
    float g3 = 1.0f / (1.0f + expf(-(aa[o * 4 + 3] * q3 + ab[o * 4 + 3])));
    outp[0] = acc[0] * g0;
    outp[1] = acc[1] * g1; outp[2] = acc[2] * g1; outp[3] = acc[3] * g1;
    outp[4] = acc[4] * g2; outp[5] = acc[5] * g2; outp[6] = acc[6] * g2;
    outp[7] = acc[7] * g3;
}

__device__ __forceinline__ void gp_stage(const float* __restrict__ gw, const float* __restrict__ xin,
                                         float* __restrict__ outp, int o) {
    constexpr Tables T = buildTables();  // folded: all indices below are literals after unroll
    float acc[8] = {0, 0, 0, 0, 0, 0, 0, 0};
    for (int i = 0; i < 64; i++) {
        float w20[20];
#pragma unroll
        for (int pp = 0; pp < 20; pp++) w20[pp] = gw[(i * 20 + pp) * 64 + o];  // coalesced
        float t8[8];
#pragma unroll
        for (int b = 0; b < 8; b++) t8[b] = xin[i * 8 + b];  // broadcast
#pragma unroll
        for (int j = 0; j < 8; j++) {
#pragma unroll
            for (int k = 0; k < 8; k++) {
                acc[j] += (T.pairSign[j][k] * w20[T.pairPid[j][k]]) *
                          (t8[k] * t8[T.pairM[j][k]]);
            }
        }
    }
#pragma unroll
    for (int j = 0; j < 8; j++) outp[j] = acc[j] * 0.125f;  // 1/sqrt(H)
}

// ---------------------------------------------------------------------------
// k_mlp: 172 blocks x 128 threads, NP=2 points/block, fully fused network.
// smem ping-pong: bufA -> lin/silu -> bufB -> gp -> bufA -> ...
// ---------------------------------------------------------------------------
__global__ void __launch_bounds__(128) k_mlp(
    const float* __restrict__ cond, const float* __restrict__ rps,
    const float* __restrict__ lin0b,
    const float* __restrict__ act0a, const float* __restrict__ act0b,
    const float* __restrict__ linsb, const float* __restrict__ actsa,
    const float* __restrict__ actsb, const float* __restrict__ outb) {
    __shared__ float bufA[NP * 512];
    __shared__ float bufB[NP * 512];

    const int t = threadIdx.x;
    const int o = t & 63;
    const int p = t >> 6;
    const float sig = rps[0];
    const float inv2s2 = 1.0f / (2.0f * sig * sig);

    // phase 0: x[p][33][8] into bufA (stride 264 per point)
    for (int idx = t; idx < NP * 264; idx += 128) {
        int pp = idx / 264; int r = idx - pp * 264; int i = r >> 3; int b = r & 7;
        int n = blockIdx.x * NP + pp; if (n > 342) n = 342;
        float v;
        if (i == 0) {
            int a0 = n / 49; int rr = n - a0 * 49; int a1 = rr / 7; int a2 = rr - a1 * 7;
            float p0 = a0 - 3.0f, p1 = a1 - 3.0f, p2 = a2 - 3.0f;
            float q = p0 * p0 + p1 * p1 + p2 * p2;
            v = (b == 0) ? expf(-q * inv2s2) : (b == 1) ? p0 : (b == 2) ? p1 : (b == 3) ? p2 : 0.0f;
        } else {
            v = cond[(i - 1) * 8 + b];
        }
        bufA[idx] = v;
    }
    __syncthreads();

    lin_silu(g_l0, lin0b, act0a, act0b, bufA + p * 264, bufB + p * 512 + o * 8, o, 33);
    __syncthreads();
    gp_stage(g_gw, bufB + p * 512, bufA + p * 512 + o * 8, o);
    __syncthreads();

    for (int l = 0; l < 3; l++) {
        lin_silu(g_lw + l * 16384, linsb + l * 64, actsa + l * 256, actsb + l * 256,
                 bufA + p * 512, bufB + p * 512 + o * 8, o, 64);
        __syncthreads();
        gp_stage(g_gw + (l + 1) * 81920, bufB + p * 512, bufA + p * 512 + o * 8, o);
        __syncthreads();
    }

    // out linear: k[n, oi, b] = sum_c out_W[g(b), oi, c] * h[n, c, b]  (+ bias at b=0)
    const int n = blockIdx.x * NP + p;
    const float* h = bufA + p * 512;
    for (int rep = 0; rep < 16; rep++) {
        int oi = rep * 64 + o;
        float acc[8] = {0, 0, 0, 0, 0, 0, 0, 0};
        for (int c = 0; c < 64; c++) {
            float w0 = g_ow[(c * 4 + 0) * 1024 + oi];
            float w1 = g_ow[(c * 4 + 1) * 1024 + oi];
            float w2 = g_ow[(c * 4 + 2) * 1024 + oi];
            float w3 = g_ow[(c * 4 + 3) * 1024 + oi];
            const float* x8 = h + c * 8;
            acc[0] += w0 * x8[0];
            acc[1] += w1 * x8[1]; acc[2] += w1 * x8[2]; acc[3] += w1 * x8[3];
            acc[4] += w2 * x8[4]; acc[5] += w2 * x8[5]; acc[6] += w2 * x8[6];
            acc[7] += w3 * x8[7];
        }
        acc[0] += outb[oi];
        if (n < 343) {
#pragma unroll
            for (int b = 0; b < 8; b++) g_kf[oi * 2752 + b * 344 + n] = acc[b];
        }
    }
}

// ---------------------------------------------------------------------------
// k_expand: one block per (o,i). Apply shell*FACTOR in smem, then 64 gathered
// coalesced store rows: K[o,l,i,m,n] = kshell[n,k*(l,m)] * cw[o,i,pid]*sign.
// ---------------------------------------------------------------------------
__global__ void __launch_bounds__(128) k_expand(
    const float* __restrict__ cw, const float* __restrict__ ss, float* __restrict__ out) {
    __shared__ float s_ks[8 * 344];
    __shared__ float s_q[344];
    __shared__ float s_cf[64];
    __shared__ int   s_ki[64];

    const int t = threadIdx.x;
    const int oi = blockIdx.x;
    const int o = oi >> 5, i = oi & 31;

    for (int n = t; n < 343; n += 128) {
        int a0 = n / 49; int rr = n - a0 * 49; int a1 = rr / 7; int a2 = rr - a1 * 7;
        float p0 = a0 - 3.0f, p1 = a1 - 3.0f, p2 = a2 - 3.0f;
        s_q[n] = p0 * p0 + p1 * p1 + p2 * p2;
    }
    if (t < 64) {
        int l = t >> 3, m = t & 7;
        int km = c_mask[l] ^ c_mask[m];
        int k = c_inv[km];
        int s = 0;
#pragma unroll
        for (int bi = 0; bi < 3; bi++)
            if (c_mask[m] & (1 << bi)) s += __popc((unsigned)(km >> (bi + 1)));
        float sgn = (s & 1) ? -1.0f : 1.0f;
        int pv = pid_rt(c_gr[k], c_gr[l], c_gr[m]);
        s_cf[t] = cw[oi * 20 + pv] * sgn;
        s_ki[t] = k;
    }
    __syncthreads();

#pragma unroll
    for (int b = 0; b < 8; b++) {
        float sg = ss[oi * 8 + b];
        float is2 = 1.0f / (sg * sg);
        for (int n = t; n < 343; n += 128)
            s_ks[b * 344 + n] = g_kf[oi * 2752 + b * 344 + n] * expf(-s_q[n] * is2) * FACTOR_;
    }
    __syncthreads();

    for (int lm = 0; lm < 64; lm++) {
        int ks = s_ki[lm];
        float cf = s_cf[lm];
        int l = lm >> 3, m = lm & 7;
        long base = (long)(((o * 8 + l) * 32 + i) * 8 + m) * 343;
        for (int n = t; n < 343; n += 128)
            out[base + n] = s_ks[ks * 344 + n] * cf;
    }
}

// ---------------------------------------------------------------------------
extern "C" void kernel_launch(void* const* d_in, const int* in_sizes, int n_in,
                              void* d_out, int out_size) {
    const float* cond = (const float*)d_in[0];
    const float* rps  = (const float*)d_in[1];
    const float* cw   = (const float*)d_in[2];
    const float* l0W  = (const float*)d_in[3];
    const float* l0b  = (const float*)d_in[4];
    const float* a0a  = (const float*)d_in[5];
    const float* a0b  = (const float*)d_in[6];
    const float* gpsw = (const float*)d_in[7];
    const float* lW   = (const float*)d_in[8];
    const float* lb   = (const float*)d_in[9];
    const float* aa   = (const float*)d_in[10];
    const float* ab   = (const float*)d_in[11];
    const float* oW   = (const float*)d_in[12];
    const float* ob   = (const float*)d_in[13];
    const float* ss   = (const float*)d_in[14];
    float* out = (float*)d_out;

    k_prep<<<2529, 256>>>(gpsw, lW, l0W, oW);          // 647,424 elems exactly
    k_mlp<<<172, 128>>>(cond, rps, l0b, a0a, a0b, lb, aa, ab, ob);
    k_expand<<<1024, 128>>>(cw, ss, out);
}

// round 12
// speedup vs baseline: 1.6993x; 1.6993x over previous
#include <cuda_runtime.h>
#include <cuda_bf16.h>
#include <math.h>

// ---------------------------------------------------------------------------
// DIM=3 Euclidean GA. 8 blades (order: (),e0,e1,e2,e01,e02,e12,e012),
// grades {0,1,1,1,2,2,2,3}. KERNEL_SIZE=7 -> 343 pts. C_IN=C_OUT=32, H=64,
// 4 layers, P=20 paths. Output (256,256,7,7,7) fp32.
// ---------------------------------------------------------------------------
typedef unsigned long long ull;
#define FACTOR_ 0.05399492471f   // 1/sqrt(343)

// -------- device scratch (no allocations allowed) --------
// all weights pre-duplicated to (w,w) float2 so LDS.64/LDG.64 give packed operands
__device__ __align__(16) ull   g_gw2[4 * 64 * 20 * 64];   // gps_w  -> [l][i][p][o] dup
__device__ __align__(16) ull   g_lw2[3 * 64 * 4 * 64];    // lins_W -> [l][i][g][o] dup
__device__ __align__(16) ull   g_l02[33 * 4 * 64];        // lin0_W -> [i][g][o] dup
__device__ __align__(16) ull   g_ow2[64 * 4 * 1024];      // out_W  -> [c][g][oi] dup
__device__ __align__(16) float g_kf[1024 * 8 * 344];      // kfield [oi][b][n] (n-stride 344)

__constant__ int c_mask[8] = {0, 1, 2, 4, 3, 5, 6, 7};
__constant__ int c_inv[8]  = {0, 1, 2, 4, 3, 5, 6, 7};
__constant__ int c_gr[8]   = {0, 1, 1, 1, 2, 2, 2, 3};

// -------- f32x2 packed helpers --------
__device__ __forceinline__ ull pk2(float a, float b) {
    ull r; asm("mov.b64 %0, {%1,%2};" : "=l"(r) : "f"(a), "f"(b)); return r;
}
__device__ __forceinline__ void upk2(ull v, float& a, float& b) {
    asm("mov.b64 {%0,%1}, %2;" : "=f"(a), "=f"(b) : "l"(v));
}
__device__ __forceinline__ ull fma2(ull a, ull b, ull c) {
    ull d; asm("fma.rn.f32x2 %0, %1, %2, %3;" : "=l"(d) : "l"(a), "l"(b), "l"(c)); return d;
}
__device__ __forceinline__ ull mul2(ull a, ull b) {
    ull d; asm("mul.rn.f32x2 %0, %1, %2;" : "=l"(d) : "l"(a), "l"(b)); return d;
}
__device__ __forceinline__ ull add2(ull a, ull b) {
    ull d; asm("add.rn.f32x2 %0, %1, %2;" : "=l"(d) : "l"(a), "l"(b)); return d;
}
#define POS8TH 0x3E0000003E000000ULL   // {0.125f, 0.125f}
#define NEG8TH 0xBE000000BE000000ULL   // {-0.125f,-0.125f}

// -------- compile-time tables for the gp layers --------
struct Tables {
    int   pid[4][4][4];
    int   pairM[8][8];
    float pairSign[8][8];
    int   pairPid[8][8];
};
__host__ __device__ constexpr int popc_(int x) {
    return (x & 1) + ((x >> 1) & 1) + ((x >> 2) & 1);
}
__host__ __device__ constexpr int signOf_(int a, int b) {
    int s = 0;
    for (int i = 0; i < 3; i++)
        if (b & (1 << i)) s += popc_(a >> (i + 1));
    return (s & 1) ? -1 : 1;
}
__host__ __device__ constexpr Tables buildTables() {
    Tables T{};
    constexpr int MSK[8] = {0, 1, 2, 4, 3, 5, 6, 7};
    constexpr int GRD[8] = {0, 1, 1, 1, 2, 2, 2, 3};
    int p = 0;
    for (int a = 0; a < 4; a++)
        for (int b = 0; b < 4; b++)
            for (int c = 0; c < 4; c++) {
                bool v = false;
                for (int t = 0; t <= 3; t++)
                    if (t <= a && t <= c && a + c - t <= 3 && a + c - 2 * t == b) v = true;
                T.pid[a][b][c] = v ? p++ : -1;
            }
    for (int j = 0; j < 8; j++)
        for (int k = 0; k < 8; k++) {
            int mm = MSK[k] ^ MSK[j];
            int m = 0;
            for (int q = 0; q < 8; q++)
                if (MSK[q] == mm) m = q;
            T.pairM[j][k] = m;
            T.pairSign[j][k] = (float)signOf_(MSK[k], mm);
            T.pairPid[j][k] = T.pid[GRD[k]][GRD[j]][GRD[m]];
        }
    return T;
}
__device__ int pid_rt(int a, int b, int c) {
    int p = 0;
    for (int aa = 0; aa < 4; aa++)
        for (int bb = 0; bb < 4; bb++)
            for (int cc = 0; cc < 4; cc++) {
                bool v = false;
                for (int t = 0; t <= 3; t++)
                    if (t <= aa && t <= cc && aa + cc - t <= 3 && aa + cc - 2 * t == bb) v = true;
                if (aa == a && bb == b && cc == c) return v ? p : 0;
                if (v) p++;
            }
    return 0;
}

// ---------------------------------------------------------------------------
// prep: transpose + duplicate weights (o-last, (w,w) pairs)
// ---------------------------------------------------------------------------
__global__ void k_prep(const float* __restrict__ gps_w, const float* __restrict__ lins_W,
                       const float* __restrict__ lin0_W, const float* __restrict__ out_W) {
    const int N1 = 327680, N2 = 49152, N3 = 8448, N4 = 262144;
    int idx = blockIdx.x * blockDim.x + threadIdx.x;
    if (idx < N1) {
        int o = idx & 63; int r = idx >> 6; int p = r % 20; r /= 20;
        int i = r & 63; int l = r >> 6;
        float w = gps_w[((l * 64 + o) * 64 + i) * 20 + p];
        ((float2*)g_gw2)[idx] = make_float2(w, w);
    } else if (idx < N1 + N2) {
        int j = idx - N1; int o = j & 63; int r = j >> 6; int g = r & 3; r >>= 2;
        int i = r & 63; int l = r >> 6;
        float w = lins_W[((l * 4 + g) * 64 + o) * 64 + i];
        ((float2*)g_lw2)[j] = make_float2(w, w);
    } else if (idx < N1 + N2 + N3) {
        int j = idx - N1 - N2; int o = j & 63; int r = j >> 6; int g = r & 3; int i = r >> 2;
        float w = lin0_W[(g * 64 + o) * 33 + i];
        ((float2*)g_l02)[j] = make_float2(w, w);
    } else if (idx < N1 + N2 + N3 + N4) {
        int j = idx - N1 - N2 - N3; int oi = j & 1023; int r = j >> 10; int g = r & 3; int c = r >> 2;
        float w = out_W[(g * 1024 + oi) * 64 + c];
        ((float2*)g_ow2)[j] = make_float2(w, w);
    }
}

// ---------------------------------------------------------------------------
// cp.async chunk copy: 10240 ull (80KB) contiguous, 128 threads
// ---------------------------------------------------------------------------
__device__ __forceinline__ void copy_chunk(ull* dst, const ull* src) {
    unsigned s = (unsigned)__cvta_generic_to_shared(dst);
    const char* g = (const char*)src;
    int t = threadIdx.x;
#pragma unroll
    for (int j = 0; j < 40; j++) {
        asm volatile("cp.async.ca.shared.global [%0], [%1], 16;"
                     :: "r"(s + (t + j * 128) * 16), "l"(g + (t + j * 128) * 16));
    }
    asm volatile("cp.async.commit_group;" ::: "memory");
}

// ---------------------------------------------------------------------------
// packed linear + silu: 2 points per thread
// ---------------------------------------------------------------------------
__device__ __forceinline__ void lin2(const ull* __restrict__ lw2, const float* __restrict__ bias,
                                     const float* __restrict__ aa, const float* __restrict__ ab,
                                     const ull* __restrict__ xin, ull* __restrict__ yout,
                                     int o, int NI) {
    ull acc[8];
#pragma unroll
    for (int b = 0; b < 8; b++) acc[b] = 0ULL;
    for (int i = 0; i < NI; i++) {
        ull w0 = lw2[(i * 4 + 0) * 64 + o];
        ull w1 = lw2[(i * 4 + 1) * 64 + o];
        ull w2 = lw2[(i * 4 + 2) * 64 + o];
        ull w3 = lw2[(i * 4 + 3) * 64 + o];
        const ull* x8 = xin + i * 8;
        acc[0] = fma2(w0, x8[0], acc[0]);
        acc[1] = fma2(w1, x8[1], acc[1]);
        acc[2] = fma2(w1, x8[2], acc[2]);
        acc[3] = fma2(w1, x8[3], acc[3]);
        acc[4] = fma2(w2, x8[4], acc[4]);
        acc[5] = fma2(w2, x8[5], acc[5]);
        acc[6] = fma2(w2, x8[6], acc[6]);
        acc[7] = fma2(w3, x8[7], acc[7]);
    }
    float bl = bias[o];
    acc[0] = add2(acc[0], pk2(bl, bl));
    float lo[8], hi[8];
#pragma unroll
    for (int b = 0; b < 8; b++) upk2(acc[b], lo[b], hi[b]);
    float q0l = lo[0] * lo[0];
    float q1l = lo[1] * lo[1] + lo[2] * lo[2] + lo[3] * lo[3];
    float q2l = lo[4] * lo[4] + lo[5] * lo[5] + lo[6] * lo[6];
    float q3l = lo[7] * lo[7];
    float q0h = hi[0] * hi[0];
    float q1h = hi[1] * hi[1] + hi[2] * hi[2] + hi[3] * hi[3];
    float q2h = hi[4] * hi[4] + hi[5] * hi[5] + hi[6] * hi[6];
    float q3h = hi[7] * hi[7];
    float a0 = aa[o * 4 + 0], a1 = aa[o * 4 + 1], a2 = aa[o * 4 + 2], a3 = aa[o * 4 + 3];
    float b0 = ab[o * 4 + 0], b1 = ab[o * 4 + 1], b2 = ab[o * 4 + 2], b3 = ab[o * 4 + 3];
    float g0l = 1.0f / (1.0f + expf(-(a0 * q0l + b0)));
    float g1l = 1.0f / (1.0f + expf(-(a1 * q1l + b1)));
    float g2l = 1.0f / (1.0f + expf(-(a2 * q2l + b2)));
    float g3l = 1.0f / (1.0f + expf(-(a3 * q3l + b3)));
    float g0h = 1.0f / (1.0f + expf(-(a0 * q0h + b0)));
    float g1h = 1.0f / (1.0f + expf(-(a1 * q1h + b1)));
    float g2h = 1.0f / (1.0f + expf(-(a2 * q2h + b2)));
    float g3h = 1.0f / (1.0f + expf(-(a3 * q3h + b3)));
    yout[0] = pk2(lo[0] * g0l, hi[0] * g0h);
    yout[1] = pk2(lo[1] * g1l, hi[1] * g1h);
    yout[2] = pk2(lo[2] * g1l, hi[2] * g1h);
    yout[3] = pk2(lo[3] * g1l, hi[3] * g1h);
    yout[4] = pk2(lo[4] * g2l, hi[4] * g2h);
    yout[5] = pk2(lo[5] * g2l, hi[5] * g2h);
    yout[6] = pk2(lo[6] * g2l, hi[6] * g2h);
    yout[7] = pk2(lo[7] * g3l, hi[7] * g3h);
}

// ---------------------------------------------------------------------------
// packed gp layer: 2 points per thread, smem-staged weights (double buffered)
// g_gw2 per-layer layout: [i][p][o] dup -> 1280 ull per i, 10240 ull per
// 8-i chunk. Chunk c covers i = 8c..8c+7 at gw2 + c*10240.
// ---------------------------------------------------------------------------
__device__ __forceinline__ void gp2(const ull* __restrict__ gw2, const ull* __restrict__ xin,
                                    ull* __restrict__ yout, int o, ull* __restrict__ wbuf) {
    constexpr Tables T = buildTables();
    ull accP[8], accN[8];
#pragma unroll
    for (int j = 0; j < 8; j++) { accP[j] = 0ULL; accN[j] = 0ULL; }

    copy_chunk(wbuf, gw2);   // chunk 0
    for (int c = 0; c < 8; c++) {
        if (c < 7) copy_chunk(wbuf + ((c + 1) & 1) * 10240, gw2 + (c + 1) * 10240);
        if (c < 7) asm volatile("cp.async.wait_group 1;" ::: "memory");
        else       asm volatile("cp.async.wait_group 0;" ::: "memory");
        __syncthreads();
        const ull* wb = wbuf + (c & 1) * 10240;
#pragma unroll
        for (int ii = 0; ii < 8; ii++) {
            ull wp[20];
#pragma unroll
            for (int p = 0; p < 20; p++) wp[p] = wb[(ii * 20 + p) * 64 + o];
            const ull* x8 = xin + (c * 8 + ii) * 8;
            ull t8[8];
#pragma unroll
            for (int b = 0; b < 8; b++) t8[b] = x8[b];
#pragma unroll
            for (int j = 0; j < 8; j++) {
                ull prod[8];
#pragma unroll
                for (int k = 0; k < 8; k++) {
                    int m = T.pairM[j][k];
                    if (k <= m) prod[k] = mul2(t8[k], t8[m]);
                }
#pragma unroll
                for (int k = 0; k < 8; k++) {
                    int m = T.pairM[j][k];
                    ull pr = (k <= m) ? prod[k] : prod[m];
                    if (T.pairSign[j][k] > 0.0f)
                        accP[j] = fma2(wp[T.pairPid[j][k]], pr, accP[j]);
                    else
                        accN[j] = fma2(wp[T.pairPid[j][k]], pr, accN[j]);
                }
            }
        }
        __syncthreads();
    }
#pragma unroll
    for (int j = 0; j < 8; j++)
        yout[j] = fma2(accN[j], (ull)NEG8TH, mul2(accP[j], (ull)POS8TH));
}

// ---------------------------------------------------------------------------
// k_mlp: 86 blocks x 128 threads; thread = (o, pair-slot pp); 2 points packed
// per thread -> 4 points per block.
// dyn smem: bufA[1024 ull] | bufB[1024 ull] | wbuf[2*10240 ull] = 180224 B
// ---------------------------------------------------------------------------
__global__ void __launch_bounds__(128) k_mlp(
    const float* __restrict__ cond, const float* __restrict__ rps,
    const float* __restrict__ lin0b,
    const float* __restrict__ act0a, const float* __restrict__ act0b,
    const float* __restrict__ linsb, const float* __restrict__ actsa,
    const float* __restrict__ actsb, const float* __restrict__ outb) {
    extern __shared__ __align__(16) ull sm[];
    ull* bufA = sm;            // [pp*512 + i*8 + b]
    ull* bufB = sm + 1024;
    ull* wbuf = sm + 2048;     // 2 x 10240

    const int t = threadIdx.x;
    const int o = t & 63;
    const int pp = t >> 6;
    const float sig = rps[0];
    const float inv2s2 = 1.0f / (2.0f * sig * sig);

    // phase 0: x[pp][33][8] packed pairs into bufA
    for (int idx = t; idx < 2 * 264; idx += 128) {
        int q = idx / 264; int r = idx - q * 264; int i = r >> 3; int b = r & 7;
        int n0 = blockIdx.x * 4 + q * 2;
        float v0, v1;
        if (i == 0) {
            int na = n0 > 342 ? 342 : n0;
            int nb = n0 + 1 > 342 ? 342 : n0 + 1;
            int a0 = na / 49, rr = na - a0 * 49, a1 = rr / 7, a2 = rr - a1 * 7;
            float p0 = a0 - 3.0f, p1 = a1 - 3.0f, p2 = a2 - 3.0f;
            float qq = p0 * p0 + p1 * p1 + p2 * p2;
            v0 = (b == 0) ? expf(-qq * inv2s2) : (b == 1) ? p0 : (b == 2) ? p1 : (b == 3) ? p2 : 0.0f;
            a0 = nb / 49; rr = nb - a0 * 49; a1 = rr / 7; a2 = rr - a1 * 7;
            p0 = a0 - 3.0f; p1 = a1 - 3.0f; p2 = a2 - 3.0f;
            qq = p0 * p0 + p1 * p1 + p2 * p2;
            v1 = (b == 0) ? expf(-qq * inv2s2) : (b == 1) ? p0 : (b == 2) ? p1 : (b == 3) ? p2 : 0.0f;
        } else {
            v0 = cond[(i - 1) * 8 + b];
            v1 = v0;
        }
        bufA[q * 512 + i * 8 + b] = pk2(v0, v1);
    }
    __syncthreads();

    lin2(g_l02, lin0b, act0a, act0b, bufA + pp * 512, bufB + pp * 512 + o * 8, o, 33);
    __syncthreads();
    gp2(g_gw2, bufB + pp * 512, bufA + pp * 512 + o * 8, o, wbuf);
    __syncthreads();

    for (int l = 0; l < 3; l++) {
        lin2(g_lw2 + l * 16384, linsb + l * 64, actsa + l * 256, actsb + l * 256,
             bufA + pp * 512, bufB + pp * 512 + o * 8, o, 64);
        __syncthreads();
        gp2(g_gw2 + (l + 1) * 81920, bufB + pp * 512, bufA + pp * 512 + o * 8, o, wbuf);
        __syncthreads();
    }

    // out linear (packed): oi = rep*64 + o; store float2 (two adjacent n) to g_kf
    const int n0 = blockIdx.x * 4 + pp * 2;          // even; n0+1 may be 343 (scratch pad)
    const ull* h = bufA + pp * 512;
    for (int rep = 0; rep < 16; rep++) {
        int oi = rep * 64 + o;
        ull acc[8];
#pragma unroll
        for (int b = 0; b < 8; b++) acc[b] = 0ULL;
        for (int c = 0; c < 64; c++) {
            ull w0 = g_ow2[(c * 4 + 0) * 1024 + oi];
            ull w1 = g_ow2[(c * 4 + 1) * 1024 + oi];
            ull w2 = g_ow2[(c * 4 + 2) * 1024 + oi];
            ull w3 = g_ow2[(c * 4 + 3) * 1024 + oi];
            const ull* x8 = h + c * 8;
            acc[0] = fma2(w0, x8[0], acc[0]);
            acc[1] = fma2(w1, x8[1], acc[1]);
            acc[2] = fma2(w1, x8[2], acc[2]);
            acc[3] = fma2(w1, x8[3], acc[3]);
            acc[4] = fma2(w2, x8[4], acc[4]);
            acc[5] = fma2(w2, x8[5], acc[5]);
            acc[6] = fma2(w2, x8[6], acc[6]);
            acc[7] = fma2(w3, x8[7], acc[7]);
        }
        float bv = outb[oi];
        acc[0] = add2(acc[0], pk2(bv, bv));
#pragma unroll
        for (int b = 0; b < 8; b++)
            *(ull*)&g_kf[oi * 2752 + b * 344 + n0] = acc[b];
    }
}

// ---------------------------------------------------------------------------
// k_expand: one block per (o,i). shell*FACTOR in smem, then 64 gathered
// coalesced store rows: K[o,l,i,m,n] = kshell[n,k*(l,m)] * cw[o,i,pid]*sign.
// ---------------------------------------------------------------------------
__global__ void __launch_bounds__(128) k_expand(
    const float* __restrict__ cw, const float* __restrict__ ss, float* __restrict__ out) {
    __shared__ float s_ks[8 * 344];
    __shared__ float s_q[344];
    __shared__ float s_cf[64];
    __shared__ int   s_ki[64];

    const int t = threadIdx.x;
    const int oi = blockIdx.x;
    const int o = oi >> 5, i = oi & 31;

    for (int n = t; n < 343; n += 128) {
        int a0 = n / 49; int rr = n - a0 * 49; int a1 = rr / 7; int a2 = rr - a1 * 7;
        float p0 = a0 - 3.0f, p1 = a1 - 3.0f, p2 = a2 - 3.0f;
        s_q[n] = p0 * p0 + p1 * p1 + p2 * p2;
    }
    if (t < 64) {
        int l = t >> 3, m = t & 7;
        int km = c_mask[l] ^ c_mask[m];
        int k = c_inv[km];
        int s = 0;
#pragma unroll
        for (int bi = 0; bi < 3; bi++)
            if (c_mask[m] & (1 << bi)) s += __popc((unsigned)(km >> (bi + 1)));
        float sgn = (s & 1) ? -1.0f : 1.0f;
        int pv = pid_rt(c_gr[k], c_gr[l], c_gr[m]);
        s_cf[t] = cw[oi * 20 + pv] * sgn;
        s_ki[t] = k;
    }
    __syncthreads();

#pragma unroll
    for (int b = 0; b < 8; b++) {
        float sg = ss[oi * 8 + b];
        float is2 = 1.0f / (sg * sg);
        for (int n = t; n < 343; n += 128)
            s_ks[b * 344 + n] = g_kf[oi * 2752 + b * 344 + n] * expf(-s_q[n] * is2) * FACTOR_;
    }
    __syncthreads();

    for (int lm = 0; lm < 64; lm++) {
        int ks = s_ki[lm];
        float cf = s_cf[lm];
        int l = lm >> 3, m = lm & 7;
        long base = (long)(((o * 8 + l) * 32 + i) * 8 + m) * 343;
        for (int n = t; n < 343; n += 128)
            out[base + n] = s_ks[ks * 344 + n] * cf;
    }
}

// ---------------------------------------------------------------------------
extern "C" void kernel_launch(void* const* d_in, const int* in_sizes, int n_in,
                              void* d_out, int out_size) {
    const float* cond = (const float*)d_in[0];
    const float* rps  = (const float*)d_in[1];
    const float* cw   = (const float*)d_in[2];
    const float* l0W  = (const float*)d_in[3];
    const float* l0b  = (const float*)d_in[4];
    const float* a0a  = (const float*)d_in[5];
    const float* a0b  = (const float*)d_in[6];
    const float* gpsw = (const float*)d_in[7];
    const float* lW   = (const float*)d_in[8];
    const float* lb   = (const float*)d_in[9];
    const float* aa   = (const float*)d_in[10];
    const float* ab   = (const float*)d_in[11];
    const float* oW   = (const float*)d_in[12];
    const float* ob   = (const float*)d_in[13];
    const float* ss   = (const float*)d_in[14];
    float* out = (float*)d_out;

    cudaFuncSetAttribute(k_mlp, cudaFuncAttributeMaxDynamicSharedMemorySize, 180224);

    k_prep<<<2529, 256>>>(gpsw, lW, l0W, oW);
    k_mlp<<<86, 128, 180224>>>(cond, rps, l0b, a0a, a0b, lb, aa, ab, ob);
    k_expand<<<1024, 128>>>(cw, ss, out);
}

// round 14
// speedup vs baseline: 2.2512x; 1.3248x over previous
#include <cuda_runtime.h>
#include <cuda_bf16.h>
#include <math.h>

// ---------------------------------------------------------------------------
// DIM=3 Euclidean GA. 8 blades (order: (),e0,e1,e2,e01,e02,e12,e012),
// grades {0,1,1,1,2,2,2,3}. KERNEL_SIZE=7 -> 343 pts. C_IN=C_OUT=32, H=64,
// 4 layers, P=20 paths. Output (256,256,7,7,7) fp32.
// ---------------------------------------------------------------------------
typedef unsigned long long ull;
#define FACTOR_ 0.05399492471f   // 1/sqrt(343)

// -------- device scratch (no allocations allowed) --------
__device__ __align__(16) ull   g_gw2[4 * 64 * 20 * 64];   // gps_w  -> [l][i][p][o] dup
__device__ __align__(16) ull   g_lw2[3 * 64 * 4 * 64];    // lins_W -> [l][i][g][o] dup
__device__ __align__(16) ull   g_l02[33 * 4 * 64];        // lin0_W -> [i][g][o] dup
__device__ __align__(16) ull   g_ow2[64 * 4 * 1024];      // out_W  -> [c][g][oi] dup
__device__ __align__(16) float g_kf[1024 * 8 * 344];      // kfield [oi][b][n] (n-stride 344)

__constant__ int c_mask[8] = {0, 1, 2, 4, 3, 5, 6, 7};
__constant__ int c_inv[8]  = {0, 1, 2, 4, 3, 5, 6, 7};
__constant__ int c_gr[8]   = {0, 1, 1, 1, 2, 2, 2, 3};

// -------- f32x2 packed helpers --------
__device__ __forceinline__ ull pk2(float a, float b) {
    ull r; asm("mov.b64 %0, {%1,%2};" : "=l"(r) : "f"(a), "f"(b)); return r;
}
__device__ __forceinline__ void upk2(ull v, float& a, float& b) {
    asm("mov.b64 {%0,%1}, %2;" : "=f"(a), "=f"(b) : "l"(v));
}
__device__ __forceinline__ ull fma2(ull a, ull b, ull c) {
    ull d; asm("fma.rn.f32x2 %0, %1, %2, %3;" : "=l"(d) : "l"(a), "l"(b), "l"(c)); return d;
}
__device__ __forceinline__ ull mul2(ull a, ull b) {
    ull d; asm("mul.rn.f32x2 %0, %1, %2;" : "=l"(d) : "l"(a), "l"(b)); return d;
}
__device__ __forceinline__ ull add2(ull a, ull b) {
    ull d; asm("add.rn.f32x2 %0, %1, %2;" : "=l"(d) : "l"(a), "l"(b)); return d;
}
#define POS8TH 0x3E0000003E000000ULL   // {0.125f, 0.125f}
#define NEG8TH 0xBE000000BE000000ULL   // {-0.125f,-0.125f}

// -------- compile-time tables for the gp layers --------
struct Tables {
    int   pid[4][4][4];
    int   pairM[8][8];
    float pairSign[8][8];
    int   pairPid[8][8];
};
__host__ __device__ constexpr int popc_(int x) {
    return (x & 1) + ((x >> 1) & 1) + ((x >> 2) & 1);
}
__host__ __device__ constexpr int signOf_(int a, int b) {
    int s = 0;
    for (int i = 0; i < 3; i++)
        if (b & (1 << i)) s += popc_(a >> (i + 1));
    return (s & 1) ? -1 : 1;
}
__host__ __device__ constexpr Tables buildTables() {
    Tables T{};
    constexpr int MSK[8] = {0, 1, 2, 4, 3, 5, 6, 7};
    constexpr int GRD[8] = {0, 1, 1, 1, 2, 2, 2, 3};
    int p = 0;
    for (int a = 0; a < 4; a++)
        for (int b = 0; b < 4; b++)
            for (int c = 0; c < 4; c++) {
                bool v = false;
                for (int t = 0; t <= 3; t++)
                    if (t <= a && t <= c && a + c - t <= 3 && a + c - 2 * t == b) v = true;
                T.pid[a][b][c] = v ? p++ : -1;
            }
    for (int j = 0; j < 8; j++)
        for (int k = 0; k < 8; k++) {
            int mm = MSK[k] ^ MSK[j];
            int m = 0;
            for (int q = 0; q < 8; q++)
                if (MSK[q] == mm) m = q;
            T.pairM[j][k] = m;
            T.pairSign[j][k] = (float)signOf_(MSK[k], mm);
            T.pairPid[j][k] = T.pid[GRD[k]][GRD[j]][GRD[m]];
        }
    return T;
}
__device__ int pid_rt(int a, int b, int c) {
    int p = 0;
    for (int aa = 0; aa < 4; aa++)
        for (int bb = 0; bb < 4; bb++)
            for (int cc = 0; cc < 4; cc++) {
                bool v = false;
                for (int t = 0; t <= 3; t++)
                    if (t <= aa && t <= cc && aa + cc - t <= 3 && aa + cc - 2 * t == bb) v = true;
                if (aa == a && bb == b && cc == c) return v ? p : 0;
                if (v) p++;
            }
    return 0;
}

// ---------------------------------------------------------------------------
// prep: transpose + duplicate weights (o-last, (w,w) pairs)
// ---------------------------------------------------------------------------
__global__ void k_prep(const float* __restrict__ gps_w, const float* __restrict__ lins_W,
                       const float* __restrict__ lin0_W, const float* __restrict__ out_W) {
    const int N1 = 327680, N2 = 49152, N3 = 8448, N4 = 262144;
    int idx = blockIdx.x * blockDim.x + threadIdx.x;
    if (idx < N1) {
        int o = idx & 63; int r = idx >> 6; int p = r % 20; r /= 20;
        int i = r & 63; int l = r >> 6;
        float w = gps_w[((l * 64 + o) * 64 + i) * 20 + p];
        ((float2*)g_gw2)[idx] = make_float2(w, w);
    } else if (idx < N1 + N2) {
        int j = idx - N1; int o = j & 63; int r = j >> 6; int g = r & 3; r >>= 2;
        int i = r & 63; int l = r >> 6;
        float w = lins_W[((l * 4 + g) * 64 + o) * 64 + i];
        ((float2*)g_lw2)[j] = make_float2(w, w);
    } else if (idx < N1 + N2 + N3) {
        int j = idx - N1 - N2; int o = j & 63; int r = j >> 6; int g = r & 3; int i = r >> 2;
        float w = lin0_W[(g * 64 + o) * 33 + i];
        ((float2*)g_l02)[j] = make_float2(w, w);
    } else if (idx < N1 + N2 + N3 + N4) {
        int j = idx - N1 - N2 - N3; int oi = j & 1023; int r = j >> 10; int g = r & 3; int c = r >> 2;
        float w = out_W[(g * 1024 + oi) * 64 + c];
        ((float2*)g_ow2)[j] = make_float2(w, w);
    }
}

// ---------------------------------------------------------------------------
// cp.async chunk copy: 10240 ull (80KB) contiguous, 256 threads
// 20 iters x 256 thr x 16B = 81,920 B exactly.
// ---------------------------------------------------------------------------
__device__ __forceinline__ void copy_chunk(ull* dst, const ull* src) {
    unsigned s = (unsigned)__cvta_generic_to_shared(dst);
    const char* g = (const char*)src;
    int t = threadIdx.x;
#pragma unroll
    for (int j = 0; j < 20; j++) {
        asm volatile("cp.async.ca.shared.global [%0], [%1], 16;"
                     :: "r"(s + (t + j * 256) * 16), "l"(g + (t + j * 256) * 16));
    }
    asm volatile("cp.async.commit_group;" ::: "memory");
}

// ---------------------------------------------------------------------------
// split linear + silu: halves split i-range, reduce via smem, h==0 applies silu
// red scratch: per-thread stride 9 ull (bank-conflict-free-ish)
// ---------------------------------------------------------------------------
__device__ __forceinline__ void lin2_split(
    const ull* __restrict__ lw2, const float* __restrict__ bias,
    const float* __restrict__ aa, const float* __restrict__ ab,
    const ull* __restrict__ xin, ull* __restrict__ yout,
    int o, int h, int i0, int i1, ull* __restrict__ red) {
    ull acc[8];
#pragma unroll
    for (int b = 0; b < 8; b++) acc[b] = 0ULL;
    for (int i = i0; i < i1; i++) {
        ull w0 = lw2[(i * 4 + 0) * 64 + o];
        ull w1 = lw2[(i * 4 + 1) * 64 + o];
        ull w2 = lw2[(i * 4 + 2) * 64 + o];
        ull w3 = lw2[(i * 4 + 3) * 64 + o];
        const ull* x8 = xin + i * 8;
        acc[0] = fma2(w0, x8[0], acc[0]);
        acc[1] = fma2(w1, x8[1], acc[1]);
        acc[2] = fma2(w1, x8[2], acc[2]);
        acc[3] = fma2(w1, x8[3], acc[3]);
        acc[4] = fma2(w2, x8[4], acc[4]);
        acc[5] = fma2(w2, x8[5], acc[5]);
        acc[6] = fma2(w2, x8[6], acc[6]);
        acc[7] = fma2(w3, x8[7], acc[7]);
    }
    const int t = threadIdx.x;
    if (h == 1) {
#pragma unroll
        for (int b = 0; b < 8; b++) red[(t - 128) * 9 + b] = acc[b];
    }
    __syncthreads();
    if (h == 0) {
#pragma unroll
        for (int b = 0; b < 8; b++) acc[b] = add2(acc[b], red[t * 9 + b]);
        float bl = bias[o];
        acc[0] = add2(acc[0], pk2(bl, bl));
        float lo[8], hi[8];
#pragma unroll
        for (int b = 0; b < 8; b++) upk2(acc[b], lo[b], hi[b]);
        float q0l = lo[0] * lo[0];
        float q1l = lo[1] * lo[1] + lo[2] * lo[2] + lo[3] * lo[3];
        float q2l = lo[4] * lo[4] + lo[5] * lo[5] + lo[6] * lo[6];
        float q3l = lo[7] * lo[7];
        float q0h = hi[0] * hi[0];
        float q1h = hi[1] * hi[1] + hi[2] * hi[2] + hi[3] * hi[3];
        float q2h = hi[4] * hi[4] + hi[5] * hi[5] + hi[6] * hi[6];
        float q3h = hi[7] * hi[7];
        float a0 = aa[o * 4 + 0], a1 = aa[o * 4 + 1], a2 = aa[o * 4 + 2], a3 = aa[o * 4 + 3];
        float b0 = ab[o * 4 + 0], b1 = ab[o * 4 + 1], b2 = ab[o * 4 + 2], b3 = ab[o * 4 + 3];
        float g0l = 1.0f / (1.0f + expf(-(a0 * q0l + b0)));
        float g1l = 1.0f / (1.0f + expf(-(a1 * q1l + b1)));
        float g2l = 1.0f / (1.0f + expf(-(a2 * q2l + b2)));
        float g3l = 1.0f / (1.0f + expf(-(a3 * q3l + b3)));
        float g0h = 1.0f / (1.0f + expf(-(a0 * q0h + b0)));
        float g1h = 1.0f / (1.0f + expf(-(a1 * q1h + b1)));
        float g2h = 1.0f / (1.0f + expf(-(a2 * q2h + b2)));
        float g3h = 1.0f / (1.0f + expf(-(a3 * q3h + b3)));
        yout[0] = pk2(lo[0] * g0l, hi[0] * g0h);
        yout[1] = pk2(lo[1] * g1l, hi[1] * g1h);
        yout[2] = pk2(lo[2] * g1l, hi[2] * g1h);
        yout[3] = pk2(lo[3] * g1l, hi[3] * g1h);
        yout[4] = pk2(lo[4] * g2l, hi[4] * g2h);
        yout[5] = pk2(lo[5] * g2l, hi[5] * g2h);
        yout[6] = pk2(lo[6] * g2l, hi[6] * g2h);
        yout[7] = pk2(lo[7] * g3l, hi[7] * g3h);
    }
    __syncthreads();
}

// ---------------------------------------------------------------------------
// split gp layer: halves split the 8 i's within each staged chunk (ii 0-3/4-7)
// partials scaled then reduced (scale is linear). wbuf doubles as reduction
// scratch after the last chunk is consumed.
// ---------------------------------------------------------------------------
__device__ __forceinline__ void gp2_split(const ull* __restrict__ gw2, const ull* __restrict__ xin,
                                          ull* __restrict__ yout, int o, int h,
                                          ull* __restrict__ wbuf) {
    constexpr Tables T = buildTables();
    ull accP[8], accN[8];
#pragma unroll
    for (int j = 0; j < 8; j++) { accP[j] = 0ULL; accN[j] = 0ULL; }

    copy_chunk(wbuf, gw2);   // chunk 0 (i = 0..7)
    for (int c = 0; c < 8; c++) {
        if (c < 7) copy_chunk(wbuf + ((c + 1) & 1) * 10240, gw2 + (c + 1) * 10240);
        if (c < 7) asm volatile("cp.async.wait_group 1;" ::: "memory");
        else       asm volatile("cp.async.wait_group 0;" ::: "memory");
        __syncthreads();
        const ull* wb = wbuf + (c & 1) * 10240;
#pragma unroll
        for (int q = 0; q < 4; q++) {
            const int ii = h * 4 + q;
            ull wp[20];
#pragma unroll
            for (int p = 0; p < 20; p++) wp[p] = wb[(ii * 20 + p) * 64 + o];
            const ull* x8 = xin + (c * 8 + ii) * 8;
            ull t8[8];
#pragma unroll
            for (int b = 0; b < 8; b++) t8[b] = x8[b];
#pragma unroll
            for (int j = 0; j < 8; j++) {
                ull prod[8];
#pragma unroll
                for (int k = 0; k < 8; k++) {
                    int m = T.pairM[j][k];
                    if (k <= m) prod[k] = mul2(t8[k], t8[m]);
                }
#pragma unroll
                for (int k = 0; k < 8; k++) {
                    int m = T.pairM[j][k];
                    ull pr = (k <= m) ? prod[k] : prod[m];
                    if (T.pairSign[j][k] > 0.0f)
                        accP[j] = fma2(wp[T.pairPid[j][k]], pr, accP[j]);
                    else
                        accN[j] = fma2(wp[T.pairPid[j][k]], pr, accN[j]);
                }
            }
        }
        __syncthreads();
    }
    // partial y (scaled) then cross-half reduce via wbuf (now dead)
    ull part[8];
#pragma unroll
    for (int j = 0; j < 8; j++)
        part[j] = fma2(accN[j], (ull)NEG8TH, mul2(accP[j], (ull)POS8TH));
    const int t = threadIdx.x;
    if (h == 1) {
#pragma unroll
        for (int j = 0; j < 8; j++) wbuf[(t - 128) * 9 + j] = part[j];
    }
    __syncthreads();
    if (h == 0) {
#pragma unroll
        for (int j = 0; j < 8; j++) yout[j] = add2(part[j], wbuf[t * 9 + j]);
    }
    __syncthreads();
}

// ---------------------------------------------------------------------------
// k_mlp: 86 blocks x 256 threads; t = h*128 + pp*64 + o.
// 2 point-pairs (4 points) per block; halves split reduction dims.
// dyn smem: bufA[1024] | bufB[1024] | wbuf[2*10240] ull = 180224 B
// ---------------------------------------------------------------------------
__global__ void __launch_bounds__(256) k_mlp(
    const float* __restrict__ cond, const float* __restrict__ rps,
    const float* __restrict__ lin0b,
    const float* __restrict__ act0a, const float* __restrict__ act0b,
    const float* __restrict__ linsb, const float* __restrict__ actsa,
    const float* __restrict__ actsb, const float* __restrict__ outb) {
    extern __shared__ __align__(16) ull sm[];
    ull* bufA = sm;            // [pp*512 + i*8 + b]
    ull* bufB = sm + 1024;
    ull* wbuf = sm + 2048;     // 2 x 10240 (also reduction scratch)

    const int t = threadIdx.x;
    const int o = t & 63;
    const int pp = (t >> 6) & 1;
    const int h = t >> 7;
    const float sig = rps[0];
    const float inv2s2 = 1.0f / (2.0f * sig * sig);

    // phase 0: x[pp][33][8] packed pairs into bufA
    for (int idx = t; idx < 2 * 264; idx += 256) {
        int q = idx / 264; int r = idx - q * 264; int i = r >> 3; int b = r & 7;
        int n0 = blockIdx.x * 4 + q * 2;
        float v0, v1;
        if (i == 0) {
            int na = n0 > 342 ? 342 : n0;
            int nb = n0 + 1 > 342 ? 342 : n0 + 1;
            int a0 = na / 49, rr = na - a0 * 49, a1 = rr / 7, a2 = rr - a1 * 7;
            float p0 = a0 - 3.0f, p1 = a1 - 3.0f, p2 = a2 - 3.0f;
            float qq = p0 * p0 + p1 * p1 + p2 * p2;
            v0 = (b == 0) ? expf(-qq * inv2s2) : (b == 1) ? p0 : (b == 2) ? p1 : (b == 3) ? p2 : 0.0f;
            a0 = nb / 49; rr = nb - a0 * 49; a1 = rr / 7; a2 = rr - a1 * 7;
            p0 = a0 - 3.0f; p1 = a1 - 3.0f; p2 = a2 - 3.0f;
            qq = p0 * p0 + p1 * p1 + p2 * p2;
            v1 = (b == 0) ? expf(-qq * inv2s2) : (b == 1) ? p0 : (b == 2) ? p1 : (b == 3) ? p2 : 0.0f;
        } else {
            v0 = cond[(i - 1) * 8 + b];
            v1 = v0;
        }
        bufA[q * 512 + i * 8 + b] = pk2(v0, v1);
    }
    __syncthreads();

    lin2_split(g_l02, lin0b, act0a, act0b, bufA + pp * 512, bufB + pp * 512 + o * 8,
               o, h, h ? 17 : 0, h ? 33 : 17, wbuf);
    gp2_split(g_gw2, bufB + pp * 512, bufA + pp * 512 + o * 8, o, h, wbuf);

    for (int l = 0; l < 3; l++) {
        lin2_split(g_lw2 + l * 16384, linsb + l * 64, actsa + l * 256, actsb + l * 256,
                   bufA + pp * 512, bufB + pp * 512 + o * 8, o, h, h * 32, h * 32 + 32, wbuf);
        gp2_split(g_gw2 + (l + 1) * 81920, bufB + pp * 512, bufA + pp * 512 + o * 8, o, h, wbuf);
    }

    // out linear (packed): halves split the 16 oi-reps 8/8; no reduction.
    const int n0 = blockIdx.x * 4 + pp * 2;          // even; n0+1 may be 343 (scratch pad)
    const ull* hbuf = bufA + pp * 512;
    for (int r = 0; r < 8; r++) {
        int oi = (h * 8 + r) * 64 + o;
        ull acc[8];
#pragma unroll
        for (int b = 0; b < 8; b++) acc[b] = 0ULL;
        for (int c = 0; c < 64; c++) {
            ull w0 = g_ow2[(c * 4 + 0) * 1024 + oi];
            ull w1 = g_ow2[(c * 4 + 1) * 1024 + oi];
            ull w2 = g_ow2[(c * 4 + 2) * 1024 + oi];
            ull w3 = g_ow2[(c * 4 + 3) * 1024 + oi];
            const ull* x8 = hbuf + c * 8;
            acc[0] = fma2(w0, x8[0], acc[0]);
            acc[1] = fma2(w1, x8[1], acc[1]);
            acc[2] = fma2(w1, x8[2], acc[2]);
            acc[3] = fma2(w1, x8[3], acc[3]);
            acc[4] = fma2(w2, x8[4], acc[4]);
            acc[5] = fma2(w2, x8[5], acc[5]);
            acc[6] = fma2(w2, x8[6], acc[6]);
            acc[7] = fma2(w3, x8[7], acc[7]);
        }
        float bv = outb[oi];
        acc[0] = add2(acc[0], pk2(bv, bv));
#pragma unroll
        for (int b = 0; b < 8; b++)
            *(ull*)&g_kf[oi * 2752 + b * 344 + n0] = acc[b];
    }
}

// ---------------------------------------------------------------------------
// k_expand: one block per (o,i). shell*FACTOR in smem, then 64 gathered
// coalesced store rows: K[o,l,i,m,n] = kshell[n,k*(l,m)] * cw[o,i,pid]*sign.
// ---------------------------------------------------------------------------
__global__ void __launch_bounds__(128) k_expand(
    const float* __restrict__ cw, const float* __restrict__ ss, float* __restrict__ out) {
    __shared__ float s_ks[8 * 344];
    __shared__ float s_q[344];
    __shared__ float s_cf[64];
    __shared__ int   s_ki[64];

    const int t = threadIdx.x;
    const int oi = blockIdx.x;
    const int o = oi >> 5, i = oi & 31;

    for (int n = t; n < 343; n += 128) {
        int a0 = n / 49; int rr = n - a0 * 49; int a1 = rr / 7; int a2 = rr - a1 * 7;
        float p0 = a0 - 3.0f, p1 = a1 - 3.0f, p2 = a2 - 3.0f;
        s_q[n] = p0 * p0 + p1 * p1 + p2 * p2;
    }
    if (t < 64) {
        int l = t >> 3, m = t & 7;
        int km = c_mask[l] ^ c_mask[m];
        int k = c_inv[km];
        int s = 0;
#pragma unroll
        for (int bi = 0; bi < 3; bi++)
            if (c_mask[m] & (1 << bi)) s += __popc((unsigned)(km >> (bi + 1)));
        float sgn = (s & 1) ? -1.0f : 1.0f;
        int pv = pid_rt(c_gr[k], c_gr[l], c_gr[m]);
        s_cf[t] = cw[oi * 20 + pv] * sgn;
        s_ki[t] = k;
    }
    __syncthreads();

#pragma unroll
    for (int b = 0; b < 8; b++) {
        float sg = ss[oi * 8 + b];
        float is2 = 1.0f / (sg * sg);
        for (int n = t; n < 343; n += 128)
            s_ks[b * 344 + n] = g_kf[oi * 2752 + b * 344 + n] * expf(-s_q[n] * is2) * FACTOR_;
    }
    __syncthreads();

    for (int lm = 0; lm < 64; lm++) {
        int ks = s_ki[lm];
        float cf = s_cf[lm];
        int l = lm >> 3, m = lm & 7;
        long base = (long)(((o * 8 + l) * 32 + i) * 8 + m) * 343;
        for (int n = t; n < 343; n += 128)
            out[base + n] = s_ks[ks * 344 + n] * cf;
    }
}

// ---------------------------------------------------------------------------
extern "C" void kernel_launch(void* const* d_in, const int* in_sizes, int n_in,
                              void* d_out, int out_size) {
    const float* cond = (const float*)d_in[0];
    const float* rps  = (const float*)d_in[1];
    const float* cw   = (const float*)d_in[2];
    const float* l0W  = (const float*)d_in[3];
    const float* l0b  = (const float*)d_in[4];
    const float* a0a  = (const float*)d_in[5];
    const float* a0b  = (const float*)d_in[6];
    const float* gpsw = (const float*)d_in[7];
    const float* lW   = (const float*)d_in[8];
    const float* lb   = (const float*)d_in[9];
    const float* aa   = (const float*)d_in[10];
    const float* ab   = (const float*)d_in[11];
    const float* oW   = (const float*)d_in[12];
    const float* ob   = (const float*)d_in[13];
    const float* ss   = (const float*)d_in[14];
    float* out = (float*)d_out;

    cudaFuncSetAttribute(k_mlp, cudaFuncAttributeMaxDynamicSharedMemorySize, 180224);

    k_prep<<<2529, 256>>>(gpsw, lW, l0W, oW);
    k_mlp<<<86, 256, 180224>>>(cond, rps, l0b, a0a, a0b, lb, aa, ab, ob);
    k_expand<<<1024, 128>>>(cw, ss, out);
}

// round 15
// speedup vs baseline: 2.5790x; 1.1456x over previous
#include <cuda_runtime.h>
#include <cuda_bf16.h>
#include <math.h>

// ---------------------------------------------------------------------------
// DIM=3 Euclidean GA. 8 blades (order: (),e0,e1,e2,e01,e02,e12,e012),
// grades {0,1,1,1,2,2,2,3}. KERNEL_SIZE=7 -> 343 pts. C_IN=C_OUT=32, H=64,
// 4 layers, P=20 paths. Output (256,256,7,7,7) fp32.
// ---------------------------------------------------------------------------
typedef unsigned long long ull;
#define FACTOR_ 0.05399492471f   // 1/sqrt(343)

// -------- device scratch (no allocations allowed) --------
__device__ __align__(16) ull   g_gw2[4 * 64 * 20 * 64];   // gps_w  -> [l][i][p][o] dup
__device__ __align__(16) ull   g_lw2[3 * 64 * 4 * 64];    // lins_W -> [l][i][g][o] dup
__device__ __align__(16) ull   g_l02[33 * 4 * 64];        // lin0_W -> [i][g][o] dup
__device__ __align__(16) ull   g_ow2[64 * 4 * 1024];      // out_W  -> [c][g][oi] dup
__device__ __align__(16) float g_kf[1024 * 8 * 344];      // kfield [oi][b][n] (n-stride 344)

__constant__ int c_mask[8] = {0, 1, 2, 4, 3, 5, 6, 7};
__constant__ int c_inv[8]  = {0, 1, 2, 4, 3, 5, 6, 7};
__constant__ int c_gr[8]   = {0, 1, 1, 1, 2, 2, 2, 3};

// -------- f32x2 packed helpers --------
__device__ __forceinline__ ull pk2(float a, float b) {
    ull r; asm("mov.b64 %0, {%1,%2};" : "=l"(r) : "f"(a), "f"(b)); return r;
}
__device__ __forceinline__ void upk2(ull v, float& a, float& b) {
    asm("mov.b64 {%0,%1}, %2;" : "=f"(a), "=f"(b) : "l"(v));
}
__device__ __forceinline__ ull fma2(ull a, ull b, ull c) {
    ull d; asm("fma.rn.f32x2 %0, %1, %2, %3;" : "=l"(d) : "l"(a), "l"(b), "l"(c)); return d;
}
__device__ __forceinline__ ull mul2(ull a, ull b) {
    ull d; asm("mul.rn.f32x2 %0, %1, %2;" : "=l"(d) : "l"(a), "l"(b)); return d;
}
__device__ __forceinline__ ull add2(ull a, ull b) {
    ull d; asm("add.rn.f32x2 %0, %1, %2;" : "=l"(d) : "l"(a), "l"(b)); return d;
}
#define POS8TH 0x3E0000003E000000ULL   // {0.125f, 0.125f}
#define NEG8TH 0xBE000000BE000000ULL   // {-0.125f,-0.125f}

// -------- compile-time tables for the gp layers --------
struct Tables {
    int   pid[4][4][4];
    int   pairM[8][8];
    float pairSign[8][8];
    int   pairPid[8][8];
};
__host__ __device__ constexpr int popc_(int x) {
    return (x & 1) + ((x >> 1) & 1) + ((x >> 2) & 1);
}
__host__ __device__ constexpr int signOf_(int a, int b) {
    int s = 0;
    for (int i = 0; i < 3; i++)
        if (b & (1 << i)) s += popc_(a >> (i + 1));
    return (s & 1) ? -1 : 1;
}
__host__ __device__ constexpr Tables buildTables() {
    Tables T{};
    constexpr int MSK[8] = {0, 1, 2, 4, 3, 5, 6, 7};
    constexpr int GRD[8] = {0, 1, 1, 1, 2, 2, 2, 3};
    int p = 0;
    for (int a = 0; a < 4; a++)
        for (int b = 0; b < 4; b++)
            for (int c = 0; c < 4; c++) {
                bool v = false;
                for (int t = 0; t <= 3; t++)
                    if (t <= a && t <= c && a + c - t <= 3 && a + c - 2 * t == b) v = true;
                T.pid[a][b][c] = v ? p++ : -1;
            }
    for (int j = 0; j < 8; j++)
        for (int k = 0; k < 8; k++) {
            int mm = MSK[k] ^ MSK[j];
            int m = 0;
            for (int q = 0; q < 8; q++)
                if (MSK[q] == mm) m = q;
            T.pairM[j][k] = m;
            T.pairSign[j][k] = (float)signOf_(MSK[k], mm);
            T.pairPid[j][k] = T.pid[GRD[k]][GRD[j]][GRD[m]];
        }
    return T;
}
__device__ int pid_rt(int a, int b, int c) {
    int p = 0;
    for (int aa = 0; aa < 4; aa++)
        for (int bb = 0; bb < 4; bb++)
            for (int cc = 0; cc < 4; cc++) {
                bool v = false;
                for (int t = 0; t <= 3; t++)
                    if (t <= aa && t <= cc && aa + cc - t <= 3 && aa + cc - 2 * t == bb) v = true;
                if (aa == a && bb == b && cc == c) return v ? p : 0;
                if (v) p++;
            }
    return 0;
}

// ---------------------------------------------------------------------------
// prep: transpose + duplicate weights (o-last, (w,w) pairs)
// ---------------------------------------------------------------------------
__global__ void k_prep(const float* __restrict__ gps_w, const float* __restrict__ lins_W,
                       const float* __restrict__ lin0_W, const float* __restrict__ out_W) {
    const int N1 = 327680, N2 = 49152, N3 = 8448, N4 = 262144;
    int idx = blockIdx.x * blockDim.x + threadIdx.x;
    if (idx < N1) {
        int o = idx & 63; int r = idx >> 6; int p = r % 20; r /= 20;
        int i = r & 63; int l = r >> 6;
        float w = gps_w[((l * 64 + o) * 64 + i) * 20 + p];
        ((float2*)g_gw2)[idx] = make_float2(w, w);
    } else if (idx < N1 + N2) {
        int j = idx - N1; int o = j & 63; int r = j >> 6; int g = r & 3; r >>= 2;
        int i = r & 63; int l = r >> 6;
        float w = lins_W[((l * 4 + g) * 64 + o) * 64 + i];
        ((float2*)g_lw2)[j] = make_float2(w, w);
    } else if (idx < N1 + N2 + N3) {
        int j = idx - N1 - N2; int o = j & 63; int r = j >> 6; int g = r & 3; int i = r >> 2;
        float w = lin0_W[(g * 64 + o) * 33 + i];
        ((float2*)g_l02)[j] = make_float2(w, w);
    } else if (idx < N1 + N2 + N3 + N4) {
        int j = idx - N1 - N2 - N3; int oi = j & 1023; int r = j >> 10; int g = r & 3; int c = r >> 2;
        float w = out_W[(g * 1024 + oi) * 64 + c];
        ((float2*)g_ow2)[j] = make_float2(w, w);
    }
}

// ---------------------------------------------------------------------------
// cp.async chunk copy: 10240 ull (80KB) contiguous, 512 threads
// 10 iters x 512 thr x 16B = 81,920 B exactly.
// ---------------------------------------------------------------------------
__device__ __forceinline__ void copy_chunk(ull* dst, const ull* src) {
    unsigned s = (unsigned)__cvta_generic_to_shared(dst);
    const char* g = (const char*)src;
    int t = threadIdx.x;
#pragma unroll
    for (int j = 0; j < 10; j++) {
        asm volatile("cp.async.ca.shared.global [%0], [%1], 16;"
                     :: "r"(s + (t + j * 512) * 16), "l"(g + (t + j * 512) * 16));
    }
    asm volatile("cp.async.commit_group;" ::: "memory");
}

// ---------------------------------------------------------------------------
// split linear + silu: quarters split i-range, reduce via smem, h==0 silu.
// red scratch: (t-128)*9 ull for h>0 (384 slots x 9 = 3456 ull < wbuf)
// ---------------------------------------------------------------------------
__device__ __forceinline__ void lin2_split(
    const ull* __restrict__ lw2, const float* __restrict__ bias,
    const float* __restrict__ aa, const float* __restrict__ ab,
    const ull* __restrict__ xin, ull* __restrict__ yout,
    int o, int h, int i0, int i1, ull* __restrict__ red) {
    ull acc[8];
#pragma unroll
    for (int b = 0; b < 8; b++) acc[b] = 0ULL;
    for (int i = i0; i < i1; i++) {
        ull w0 = lw2[(i * 4 + 0) * 64 + o];
        ull w1 = lw2[(i * 4 + 1) * 64 + o];
        ull w2 = lw2[(i * 4 + 2) * 64 + o];
        ull w3 = lw2[(i * 4 + 3) * 64 + o];
        const ull* x8 = xin + i * 8;
        acc[0] = fma2(w0, x8[0], acc[0]);
        acc[1] = fma2(w1, x8[1], acc[1]);
        acc[2] = fma2(w1, x8[2], acc[2]);
        acc[3] = fma2(w1, x8[3], acc[3]);
        acc[4] = fma2(w2, x8[4], acc[4]);
        acc[5] = fma2(w2, x8[5], acc[5]);
        acc[6] = fma2(w2, x8[6], acc[6]);
        acc[7] = fma2(w3, x8[7], acc[7]);
    }
    const int t = threadIdx.x;
    if (h > 0) {
#pragma unroll
        for (int b = 0; b < 8; b++) red[(t - 128) * 9 + b] = acc[b];
    }
    __syncthreads();
    if (h == 0) {
#pragma unroll
        for (int b = 0; b < 8; b++) {
            acc[b] = add2(acc[b], red[t * 9 + b]);
            acc[b] = add2(acc[b], red[(t + 128) * 9 + b]);
            acc[b] = add2(acc[b], red[(t + 256) * 9 + b]);
        }
        float bl = bias[o];
        acc[0] = add2(acc[0], pk2(bl, bl));
        float lo[8], hi[8];
#pragma unroll
        for (int b = 0; b < 8; b++) upk2(acc[b], lo[b], hi[b]);
        float q0l = lo[0] * lo[0];
        float q1l = lo[1] * lo[1] + lo[2] * lo[2] + lo[3] * lo[3];
        float q2l = lo[4] * lo[4] + lo[5] * lo[5] + lo[6] * lo[6];
        float q3l = lo[7] * lo[7];
        float q0h = hi[0] * hi[0];
        float q1h = hi[1] * hi[1] + hi[2] * hi[2] + hi[3] * hi[3];
        float q2h = hi[4] * hi[4] + hi[5] * hi[5] + hi[6] * hi[6];
        float q3h = hi[7] * hi[7];
        float a0 = aa[o * 4 + 0], a1 = aa[o * 4 + 1], a2 = aa[o * 4 + 2], a3 = aa[o * 4 + 3];
        float b0 = ab[o * 4 + 0], b1 = ab[o * 4 + 1], b2 = ab[o * 4 + 2], b3 = ab[o * 4 + 3];
        float g0l = 1.0f / (1.0f + expf(-(a0 * q0l + b0)));
        float g1l = 1.0f / (1.0f + expf(-(a1 * q1l + b1)));
        float g2l = 1.0f / (1.0f + expf(-(a2 * q2l + b2)));
        float g3l = 1.0f / (1.0f + expf(-(a3 * q3l + b3)));
        float g0h = 1.0f / (1.0f + expf(-(a0 * q0h + b0)));
        float g1h = 1.0f / (1.0f + expf(-(a1 * q1h + b1)));
        float g2h = 1.0f / (1.0f + expf(-(a2 * q2h + b2)));
        float g3h = 1.0f / (1.0f + expf(-(a3 * q3h + b3)));
        yout[0] = pk2(lo[0] * g0l, hi[0] * g0h);
        yout[1] = pk2(lo[1] * g1l, hi[1] * g1h);
        yout[2] = pk2(lo[2] * g1l, hi[2] * g1h);
        yout[3] = pk2(lo[3] * g1l, hi[3] * g1h);
        yout[4] = pk2(lo[4] * g2l, hi[4] * g2h);
        yout[5] = pk2(lo[5] * g2l, hi[5] * g2h);
        yout[6] = pk2(lo[6] * g2l, hi[6] * g2h);
        yout[7] = pk2(lo[7] * g3l, hi[7] * g3h);
    }
    __syncthreads();
}

// ---------------------------------------------------------------------------
// split gp layer: quarters handle 2 of the 8 i's per staged chunk
// (ii = 2h, 2h+1). Scaled partials reduced 4-way via dead wbuf.
// ---------------------------------------------------------------------------
__device__ __forceinline__ void gp2_split(const ull* __restrict__ gw2, const ull* __restrict__ xin,
                                          ull* __restrict__ yout, int o, int h,
                                          ull* __restrict__ wbuf) {
    constexpr Tables T = buildTables();
    ull accP[8], accN[8];
#pragma unroll
    for (int j = 0; j < 8; j++) { accP[j] = 0ULL; accN[j] = 0ULL; }

    copy_chunk(wbuf, gw2);   // chunk 0 (i = 0..7)
    for (int c = 0; c < 8; c++) {
        if (c < 7) copy_chunk(wbuf + ((c + 1) & 1) * 10240, gw2 + (c + 1) * 10240);
        if (c < 7) asm volatile("cp.async.wait_group 1;" ::: "memory");
        else       asm volatile("cp.async.wait_group 0;" ::: "memory");
        __syncthreads();
        const ull* wb = wbuf + (c & 1) * 10240;
#pragma unroll
        for (int q = 0; q < 2; q++) {
            const int ii = h * 2 + q;
            ull wp[20];
#pragma unroll
            for (int p = 0; p < 20; p++) wp[p] = wb[(ii * 20 + p) * 64 + o];
            const ull* x8 = xin + (c * 8 + ii) * 8;
            ull t8[8];
#pragma unroll
            for (int b = 0; b < 8; b++) t8[b] = x8[b];
#pragma unroll
            for (int j = 0; j < 8; j++) {
                ull prod[8];
#pragma unroll
                for (int k = 0; k < 8; k++) {
                    int m = T.pairM[j][k];
                    if (k <= m) prod[k] = mul2(t8[k], t8[m]);
                }
#pragma unroll
                for (int k = 0; k < 8; k++) {
                    int m = T.pairM[j][k];
                    ull pr = (k <= m) ? prod[k] : prod[m];
                    if (T.pairSign[j][k] > 0.0f)
                        accP[j] = fma2(wp[T.pairPid[j][k]], pr, accP[j]);
                    else
                        accN[j] = fma2(wp[T.pairPid[j][k]], pr, accN[j]);
                }
            }
        }
        __syncthreads();
    }
    // partial y (scaled) then 4-way reduce via wbuf (now dead)
    ull part[8];
#pragma unroll
    for (int j = 0; j < 8; j++)
        part[j] = fma2(accN[j], (ull)NEG8TH, mul2(accP[j], (ull)POS8TH));
    const int t = threadIdx.x;
    if (h > 0) {
#pragma unroll
        for (int j = 0; j < 8; j++) wbuf[(t - 128) * 9 + j] = part[j];
    }
    __syncthreads();
    if (h == 0) {
#pragma unroll
        for (int j = 0; j < 8; j++) {
            part[j] = add2(part[j], wbuf[t * 9 + j]);
            part[j] = add2(part[j], wbuf[(t + 128) * 9 + j]);
            yout[j] = add2(part[j], wbuf[(t + 256) * 9 + j]);
        }
    }
    __syncthreads();
}

// ---------------------------------------------------------------------------
// k_mlp: 86 blocks x 512 threads; t = h*128 + pp*64 + o (h = reduction quarter).
// 2 point-pairs (4 points) per block.
// dyn smem: bufA[1024] | bufB[1024] | wbuf[2*10240] ull = 180224 B
// ---------------------------------------------------------------------------
__global__ void __launch_bounds__(512) k_mlp(
    const float* __restrict__ cond, const float* __restrict__ rps,
    const float* __restrict__ lin0b,
    const float* __restrict__ act0a, const float* __restrict__ act0b,
    const float* __restrict__ linsb, const float* __restrict__ actsa,
    const float* __restrict__ actsb, const float* __restrict__ outb) {
    extern __shared__ __align__(16) ull sm[];
    ull* bufA = sm;            // [pp*512 + i*8 + b]
    ull* bufB = sm + 1024;
    ull* wbuf = sm + 2048;     // 2 x 10240 (also reduction scratch)

    const int t = threadIdx.x;
    const int o = t & 63;
    const int pp = (t >> 6) & 1;
    const int h = t >> 7;      // 0..3
    const float sig = rps[0];
    const float inv2s2 = 1.0f / (2.0f * sig * sig);

    // phase 0: x[pp][33][8] packed pairs into bufA
    for (int idx = t; idx < 2 * 264; idx += 512) {
        int q = idx / 264; int r = idx - q * 264; int i = r >> 3; int b = r & 7;
        int n0 = blockIdx.x * 4 + q * 2;
        float v0, v1;
        if (i == 0) {
            int na = n0 > 342 ? 342 : n0;
            int nb = n0 + 1 > 342 ? 342 : n0 + 1;
            int a0 = na / 49, rr = na - a0 * 49, a1 = rr / 7, a2 = rr - a1 * 7;
            float p0 = a0 - 3.0f, p1 = a1 - 3.0f, p2 = a2 - 3.0f;
            float qq = p0 * p0 + p1 * p1 + p2 * p2;
            v0 = (b == 0) ? expf(-qq * inv2s2) : (b == 1) ? p0 : (b == 2) ? p1 : (b == 3) ? p2 : 0.0f;
            a0 = nb / 49; rr = nb - a0 * 49; a1 = rr / 7; a2 = rr - a1 * 7;
            p0 = a0 - 3.0f; p1 = a1 - 3.0f; p2 = a2 - 3.0f;
            qq = p0 * p0 + p1 * p1 + p2 * p2;
            v1 = (b == 0) ? expf(-qq * inv2s2) : (b == 1) ? p0 : (b == 2) ? p1 : (b == 3) ? p2 : 0.0f;
        } else {
            v0 = cond[(i - 1) * 8 + b];
            v1 = v0;
        }
        bufA[q * 512 + i * 8 + b] = pk2(v0, v1);
    }
    __syncthreads();

    {
        const int l0s[5] = {0, 9, 17, 25, 33};
        lin2_split(g_l02, lin0b, act0a, act0b, bufA + pp * 512, bufB + pp * 512 + o * 8,
                   o, h, l0s[h], l0s[h + 1], wbuf);
    }
    gp2_split(g_gw2, bufB + pp * 512, bufA + pp * 512 + o * 8, o, h, wbuf);

    for (int l = 0; l < 3; l++) {
        lin2_split(g_lw2 + l * 16384, linsb + l * 64, actsa + l * 256, actsb + l * 256,
                   bufA + pp * 512, bufB + pp * 512 + o * 8, o, h, h * 16, h * 16 + 16, wbuf);
        gp2_split(g_gw2 + (l + 1) * 81920, bufB + pp * 512, bufA + pp * 512 + o * 8, o, h, wbuf);
    }

    // out linear (packed): quarters split the 16 oi-reps 4/4/4/4; no reduction.
    const int n0 = blockIdx.x * 4 + pp * 2;          // even; n0+1 may be 343 (scratch pad)
    const ull* hbuf = bufA + pp * 512;
    for (int r = 0; r < 4; r++) {
        int oi = (h * 4 + r) * 64 + o;
        ull acc[8];
#pragma unroll
        for (int b = 0; b < 8; b++) acc[b] = 0ULL;
        for (int c = 0; c < 64; c++) {
            ull w0 = g_ow2[(c * 4 + 0) * 1024 + oi];
            ull w1 = g_ow2[(c * 4 + 1) * 1024 + oi];
            ull w2 = g_ow2[(c * 4 + 2) * 1024 + oi];
            ull w3 = g_ow2[(c * 4 + 3) * 1024 + oi];
            const ull* x8 = hbuf + c * 8;
            acc[0] = fma2(w0, x8[0], acc[0]);
            acc[1] = fma2(w1, x8[1], acc[1]);
            acc[2] = fma2(w1, x8[2], acc[2]);
            acc[3] = fma2(w1, x8[3], acc[3]);
            acc[4] = fma2(w2, x8[4], acc[4]);
            acc[5] = fma2(w2, x8[5], acc[5]);
            acc[6] = fma2(w2, x8[6], acc[6]);
            acc[7] = fma2(w3, x8[7], acc[7]);
        }
        float bv = outb[oi];
        acc[0] = add2(acc[0], pk2(bv, bv));
#pragma unroll
        for (int b = 0; b < 8; b++)
            *(ull*)&g_kf[oi * 2752 + b * 344 + n0] = acc[b];
    }
}

// ---------------------------------------------------------------------------
// k_expand: one block per (o,i). shell*FACTOR in smem, then 64 gathered
// coalesced store rows: K[o,l,i,m,n] = kshell[n,k*(l,m)] * cw[o,i,pid]*sign.
// ---------------------------------------------------------------------------
__global__ void __launch_bounds__(128) k_expand(
    const float* __restrict__ cw, const float* __restrict__ ss, float* __restrict__ out) {
    __shared__ float s_ks[8 * 344];
    __shared__ float s_q[344];
    __shared__ float s_cf[64];
    __shared__ int   s_ki[64];

    const int t = threadIdx.x;
    const int oi = blockIdx.x;
    const int o = oi >> 5, i = oi & 31;

    for (int n = t; n < 343; n += 128) {
        int a0 = n / 49; int rr = n - a0 * 49; int a1 = rr / 7; int a2 = rr - a1 * 7;
        float p0 = a0 - 3.0f, p1 = a1 - 3.0f, p2 = a2 - 3.0f;
        s_q[n] = p0 * p0 + p1 * p1 + p2 * p2;
    }
    if (t < 64) {
        int l = t >> 3, m = t & 7;
        int km = c_mask[l] ^ c_mask[m];
        int k = c_inv[km];
        int s = 0;
#pragma unroll
        for (int bi = 0; bi < 3; bi++)
            if (c_mask[m] & (1 << bi)) s += __popc((unsigned)(km >> (bi + 1)));
        float sgn = (s & 1) ? -1.0f : 1.0f;
        int pv = pid_rt(c_gr[k], c_gr[l], c_gr[m]);
        s_cf[t] = cw[oi * 20 + pv] * sgn;
        s_ki[t] = k;
    }
    __syncthreads();

#pragma unroll
    for (int b = 0; b < 8; b++) {
        float sg = ss[oi * 8 + b];
        float is2 = 1.0f / (sg * sg);
        for (int n = t; n < 343; n += 128)
            s_ks[b * 344 + n] = g_kf[oi * 2752 + b * 344 + n] * expf(-s_q[n] * is2) * FACTOR_;
    }
    __syncthreads();

    for (int lm = 0; lm < 64; lm++) {
        int ks = s_ki[lm];
        float cf = s_cf[lm];
        int l = lm >> 3, m = lm & 7;
        long base = (long)(((o * 8 + l) * 32 + i) * 8 + m) * 343;
        for (int n = t; n < 343; n += 128)
            out[base + n] = s_ks[ks * 344 + n] * cf;
    }
}

// ---------------------------------------------------------------------------
extern "C" void kernel_launch(void* const* d_in, const int* in_sizes, int n_in,
                              void* d_out, int out_size) {
    const float* cond = (const float*)d_in[0];
    const float* rps  = (const float*)d_in[1];
    const float* cw   = (const float*)d_in[2];
    const float* l0W  = (const float*)d_in[3];
    const float* l0b  = (const float*)d_in[4];
    const float* a0a  = (const float*)d_in[5];
    const float* a0b  = (const float*)d_in[6];
    const float* gpsw = (const float*)d_in[7];
    const float* lW   = (const float*)d_in[8];
    const float* lb   = (const float*)d_in[9];
    const float* aa   = (const float*)d_in[10];
    const float* ab   = (const float*)d_in[11];
    const float* oW   = (const float*)d_in[12];
    const float* ob   = (const float*)d_in[13];
    const float* ss   = (const float*)d_in[14];
    float* out = (float*)d_out;

    cudaFuncSetAttribute(k_mlp, cudaFuncAttributeMaxDynamicSharedMemorySize, 180224);

    k_prep<<<2529, 256>>>(gpsw, lW, l0W, oW);
    k_mlp<<<86, 512, 180224>>>(cond, rps, l0b, a0a, a0b, lb, aa, ab, ob);
    k_expand<<<1024, 128>>>(cw, ss, out);
}

// round 16
// speedup vs baseline: 3.0156x; 1.1693x over previous
#include <cuda_runtime.h>
#include <cuda_bf16.h>
#include <math.h>

// ---------------------------------------------------------------------------
// DIM=3 Euclidean GA. 8 blades (order: (),e0,e1,e2,e01,e02,e12,e012),
// grades {0,1,1,1,2,2,2,3}. KERNEL_SIZE=7 -> 343 pts. C_IN=C_OUT=32, H=64,
// 4 layers, P=20 paths. Output (256,256,7,7,7) fp32.
// ---------------------------------------------------------------------------
typedef unsigned long long ull;
#define FACTOR_ 0.05399492471f   // 1/sqrt(343)

// -------- device scratch (no allocations allowed); plain float weights ------
__device__ __align__(16) float g_gw[4 * 64 * 20 * 64];   // gps_w  -> [l][i][p][o]
__device__ __align__(16) float g_lw[3 * 64 * 4 * 64];    // lins_W -> [l][i][g][o]
__device__ __align__(16) float g_l0[33 * 4 * 64];        // lin0_W -> [i][g][o]
__device__ __align__(16) float g_ow[64 * 4 * 1024];      // out_W  -> [c][g][oi]
__device__ __align__(16) float g_kf[1024 * 8 * 344];     // kfield [oi][b][n] (n-stride 344)

__constant__ int c_mask[8] = {0, 1, 2, 4, 3, 5, 6, 7};
__constant__ int c_inv[8]  = {0, 1, 2, 4, 3, 5, 6, 7};
__constant__ int c_gr[8]   = {0, 1, 1, 1, 2, 2, 2, 3};

// -------- f32x2 packed helpers --------
__device__ __forceinline__ ull pk2(float a, float b) {
    ull r; asm("mov.b64 %0, {%1,%2};" : "=l"(r) : "f"(a), "f"(b)); return r;
}
__device__ __forceinline__ ull dup2(float a) {          // (w,w)
    ull r; asm("mov.b64 %0, {%1,%1};" : "=l"(r) : "f"(a)); return r;
}
__device__ __forceinline__ void upk2(ull v, float& a, float& b) {
    asm("mov.b64 {%0,%1}, %2;" : "=f"(a), "=f"(b) : "l"(v));
}
__device__ __forceinline__ ull fma2(ull a, ull b, ull c) {
    ull d; asm("fma.rn.f32x2 %0, %1, %2, %3;" : "=l"(d) : "l"(a), "l"(b), "l"(c)); return d;
}
__device__ __forceinline__ ull mul2(ull a, ull b) {
    ull d; asm("mul.rn.f32x2 %0, %1, %2;" : "=l"(d) : "l"(a), "l"(b)); return d;
}
__device__ __forceinline__ ull add2(ull a, ull b) {
    ull d; asm("add.rn.f32x2 %0, %1, %2;" : "=l"(d) : "l"(a), "l"(b)); return d;
}
#define POS8TH 0x3E0000003E000000ULL   // {0.125f, 0.125f}
#define NEG8TH 0xBE000000BE000000ULL   // {-0.125f,-0.125f}

// -------- compile-time tables for the gp layers --------
struct Tables {
    int   pid[4][4][4];
    int   pairM[8][8];
    float pairSign[8][8];
    int   pairPid[8][8];
};
__host__ __device__ constexpr int popc_(int x) {
    return (x & 1) + ((x >> 1) & 1) + ((x >> 2) & 1);
}
__host__ __device__ constexpr int signOf_(int a, int b) {
    int s = 0;
    for (int i = 0; i < 3; i++)
        if (b & (1 << i)) s += popc_(a >> (i + 1));
    return (s & 1) ? -1 : 1;
}
__host__ __device__ constexpr Tables buildTables() {
    Tables T{};
    constexpr int MSK[8] = {0, 1, 2, 4, 3, 5, 6, 7};
    constexpr int GRD[8] = {0, 1, 1, 1, 2, 2, 2, 3};
    int p = 0;
    for (int a = 0; a < 4; a++)
        for (int b = 0; b < 4; b++)
            for (int c = 0; c < 4; c++) {
                bool v = false;
                for (int t = 0; t <= 3; t++)
                    if (t <= a && t <= c && a + c - t <= 3 && a + c - 2 * t == b) v = true;
                T.pid[a][b][c] = v ? p++ : -1;
            }
    for (int j = 0; j < 8; j++)
        for (int k = 0; k < 8; k++) {
            int mm = MSK[k] ^ MSK[j];
            int m = 0;
            for (int q = 0; q < 8; q++)
                if (MSK[q] == mm) m = q;
            T.pairM[j][k] = m;
            T.pairSign[j][k] = (float)signOf_(MSK[k], mm);
            T.pairPid[j][k] = T.pid[GRD[k]][GRD[j]][GRD[m]];
        }
    return T;
}
__device__ int pid_rt(int a, int b, int c) {
    int p = 0;
    for (int aa = 0; aa < 4; aa++)
        for (int bb = 0; bb < 4; bb++)
            for (int cc = 0; cc < 4; cc++) {
                bool v = false;
                for (int t = 0; t <= 3; t++)
                    if (t <= aa && t <= cc && aa + cc - t <= 3 && aa + cc - 2 * t == bb) v = true;
                if (aa == a && bb == b && cc == c) return v ? p : 0;
                if (v) p++;
            }
    return 0;
}

// ---------------------------------------------------------------------------
// prep: transpose weights (o-last), plain float
// ---------------------------------------------------------------------------
__global__ void k_prep(const float* __restrict__ gps_w, const float* __restrict__ lins_W,
                       const float* __restrict__ lin0_W, const float* __restrict__ out_W) {
    const int N1 = 327680, N2 = 49152, N3 = 8448, N4 = 262144;
    int idx = blockIdx.x * blockDim.x + threadIdx.x;
    if (idx < N1) {
        int o = idx & 63; int r = idx >> 6; int p = r % 20; r /= 20;
        int i = r & 63; int l = r >> 6;
        g_gw[idx] = gps_w[((l * 64 + o) * 64 + i) * 20 + p];
    } else if (idx < N1 + N2) {
        int j = idx - N1; int o = j & 63; int r = j >> 6; int g = r & 3; r >>= 2;
        int i = r & 63; int l = r >> 6;
        g_lw[j] = lins_W[((l * 4 + g) * 64 + o) * 64 + i];
    } else if (idx < N1 + N2 + N3) {
        int j = idx - N1 - N2; int o = j & 63; int r = j >> 6; int g = r & 3; int i = r >> 2;
        g_l0[j] = lin0_W[(g * 64 + o) * 33 + i];
    } else if (idx < N1 + N2 + N3 + N4) {
        int j = idx - N1 - N2 - N3; int oi = j & 1023; int r = j >> 10; int g = r & 3; int c = r >> 2;
        g_ow[j] = out_W[(g * 1024 + oi) * 64 + c];
    }
}

// ---------------------------------------------------------------------------
// cp.async chunk copy: 81,920 B contiguous, 512 threads
// 10 iters x 512 thr x 16B = 81,920 B exactly.
// ---------------------------------------------------------------------------
__device__ __forceinline__ void copy_chunk(void* dst, const void* src) {
    unsigned s = (unsigned)__cvta_generic_to_shared(dst);
    const char* g = (const char*)src;
    int t = threadIdx.x;
#pragma unroll
    for (int j = 0; j < 10; j++) {
        asm volatile("cp.async.ca.shared.global [%0], [%1], 16;"
                     :: "r"(s + (t + j * 512) * 16), "l"(g + (t + j * 512) * 16));
    }
    asm volatile("cp.async.commit_group;" ::: "memory");
}

// ---------------------------------------------------------------------------
// split linear + silu: quarters split i-range, reduce via smem, h==0 silu.
// weights: plain float, dup'd in registers.
// ---------------------------------------------------------------------------
__device__ __forceinline__ void lin2_split(
    const float* __restrict__ lwf, const float* __restrict__ bias,
    const float* __restrict__ aa, const float* __restrict__ ab,
    const ull* __restrict__ xin, ull* __restrict__ yout,
    int o, int h, int i0, int i1, ull* __restrict__ red) {
    ull acc[8];
#pragma unroll
    for (int b = 0; b < 8; b++) acc[b] = 0ULL;
    for (int i = i0; i < i1; i++) {
        ull w0 = dup2(lwf[(i * 4 + 0) * 64 + o]);
        ull w1 = dup2(lwf[(i * 4 + 1) * 64 + o]);
        ull w2 = dup2(lwf[(i * 4 + 2) * 64 + o]);
        ull w3 = dup2(lwf[(i * 4 + 3) * 64 + o]);
        const ull* x8 = xin + i * 8;
        acc[0] = fma2(w0, x8[0], acc[0]);
        acc[1] = fma2(w1, x8[1], acc[1]);
        acc[2] = fma2(w1, x8[2], acc[2]);
        acc[3] = fma2(w1, x8[3], acc[3]);
        acc[4] = fma2(w2, x8[4], acc[4]);
        acc[5] = fma2(w2, x8[5], acc[5]);
        acc[6] = fma2(w2, x8[6], acc[6]);
        acc[7] = fma2(w3, x8[7], acc[7]);
    }
    const int t = threadIdx.x;
    if (h > 0) {
#pragma unroll
        for (int b = 0; b < 8; b++) red[(t - 128) * 9 + b] = acc[b];
    }
    __syncthreads();
    if (h == 0) {
#pragma unroll
        for (int b = 0; b < 8; b++) {
            acc[b] = add2(acc[b], red[t * 9 + b]);
            acc[b] = add2(acc[b], red[(t + 128) * 9 + b]);
            acc[b] = add2(acc[b], red[(t + 256) * 9 + b]);
        }
        float bl = bias[o];
        acc[0] = add2(acc[0], pk2(bl, bl));
        float lo[8], hi[8];
#pragma unroll
        for (int b = 0; b < 8; b++) upk2(acc[b], lo[b], hi[b]);
        float q0l = lo[0] * lo[0];
        float q1l = lo[1] * lo[1] + lo[2] * lo[2] + lo[3] * lo[3];
        float q2l = lo[4] * lo[4] + lo[5] * lo[5] + lo[6] * lo[6];
        float q3l = lo[7] * lo[7];
        float q0h = hi[0] * hi[0];
        float q1h = hi[1] * hi[1] + hi[2] * hi[2] + hi[3] * hi[3];
        float q2h = hi[4] * hi[4] + hi[5] * hi[5] + hi[6] * hi[6];
        float q3h = hi[7] * hi[7];
        float a0 = aa[o * 4 + 0], a1 = aa[o * 4 + 1], a2 = aa[o * 4 + 2], a3 = aa[o * 4 + 3];
        float b0 = ab[o * 4 + 0], b1 = ab[o * 4 + 1], b2 = ab[o * 4 + 2], b3 = ab[o * 4 + 3];
        float g0l = 1.0f / (1.0f + expf(-(a0 * q0l + b0)));
        float g1l = 1.0f / (1.0f + expf(-(a1 * q1l + b1)));
        float g2l = 1.0f / (1.0f + expf(-(a2 * q2l + b2)));
        float g3l = 1.0f / (1.0f + expf(-(a3 * q3l + b3)));
        float g0h = 1.0f / (1.0f + expf(-(a0 * q0h + b0)));
        float g1h = 1.0f / (1.0f + expf(-(a1 * q1h + b1)));
        float g2h = 1.0f / (1.0f + expf(-(a2 * q2h + b2)));
        float g3h = 1.0f / (1.0f + expf(-(a3 * q3h + b3)));
        yout[0] = pk2(lo[0] * g0l, hi[0] * g0h);
        yout[1] = pk2(lo[1] * g1l, hi[1] * g1h);
        yout[2] = pk2(lo[2] * g1l, hi[2] * g1h);
        yout[3] = pk2(lo[3] * g1l, hi[3] * g1h);
        yout[4] = pk2(lo[4] * g2l, hi[4] * g2h);
        yout[5] = pk2(lo[5] * g2l, hi[5] * g2h);
        yout[6] = pk2(lo[6] * g2l, hi[6] * g2h);
        yout[7] = pk2(lo[7] * g3l, hi[7] * g3h);
    }
    __syncthreads();
}

// ---------------------------------------------------------------------------
// split gp layer: 4 staged chunks of 16 i's (80 KB floats each, double-buffer);
// quarter h handles ii = 4h..4h+3 within each chunk; 4-way smem reduce.
// ---------------------------------------------------------------------------
__device__ __forceinline__ void gp2_split(const float* __restrict__ gwf, const ull* __restrict__ xin,
                                          ull* __restrict__ yout, int o, int h,
                                          ull* __restrict__ wbuf) {
    constexpr Tables T = buildTables();
    ull accP[8], accN[8];
#pragma unroll
    for (int j = 0; j < 8; j++) { accP[j] = 0ULL; accN[j] = 0ULL; }

    copy_chunk(wbuf, gwf);   // chunk 0 (i = 0..15)
    for (int c = 0; c < 4; c++) {
        if (c < 3) copy_chunk(wbuf + ((c + 1) & 1) * 10240, gwf + (c + 1) * 20480);
        if (c < 3) asm volatile("cp.async.wait_group 1;" ::: "memory");
        else       asm volatile("cp.async.wait_group 0;" ::: "memory");
        __syncthreads();
        const float* wf = (const float*)(wbuf + (c & 1) * 10240);
#pragma unroll
        for (int q = 0; q < 4; q++) {
            const int ii = h * 4 + q;
            ull wp[20];
#pragma unroll
            for (int p = 0; p < 20; p++) wp[p] = dup2(wf[(ii * 20 + p) * 64 + o]);
            const ull* x8 = xin + (c * 16 + ii) * 8;
            ull t8[8];
#pragma unroll
            for (int b = 0; b < 8; b++) t8[b] = x8[b];
#pragma unroll
            for (int j = 0; j < 8; j++) {
                ull prod[8];
#pragma unroll
                for (int k = 0; k < 8; k++) {
                    int m = T.pairM[j][k];
                    if (k <= m) prod[k] = mul2(t8[k], t8[m]);
                }
#pragma unroll
                for (int k = 0; k < 8; k++) {
                    int m = T.pairM[j][k];
                    ull pr = (k <= m) ? prod[k] : prod[m];
                    if (T.pairSign[j][k] > 0.0f)
                        accP[j] = fma2(wp[T.pairPid[j][k]], pr, accP[j]);
                    else
                        accN[j] = fma2(wp[T.pairPid[j][k]], pr, accN[j]);
                }
            }
        }
        __syncthreads();
    }
    // partial y (scaled) then 4-way reduce via wbuf (now dead)
    ull part[8];
#pragma unroll
    for (int j = 0; j < 8; j++)
        part[j] = fma2(accN[j], (ull)NEG8TH, mul2(accP[j], (ull)POS8TH));
    const int t = threadIdx.x;
    if (h > 0) {
#pragma unroll
        for (int j = 0; j < 8; j++) wbuf[(t - 128) * 9 + j] = part[j];
    }
    __syncthreads();
    if (h == 0) {
#pragma unroll
        for (int j = 0; j < 8; j++) {
            part[j] = add2(part[j], wbuf[t * 9 + j]);
            part[j] = add2(part[j], wbuf[(t + 128) * 9 + j]);
            yout[j] = add2(part[j], wbuf[(t + 256) * 9 + j]);
        }
    }
    __syncthreads();
}

// ---------------------------------------------------------------------------
// k_mlp: 86 blocks x 512 threads; t = h*128 + pp*64 + o (h = reduction quarter).
// 2 point-pairs (4 points) per block.
// dyn smem: bufA[1024] | bufB[1024] | wbuf[2*10240] ull = 180224 B
// ---------------------------------------------------------------------------
__global__ void __launch_bounds__(512) k_mlp(
    const float* __restrict__ cond, const float* __restrict__ rps,
    const float* __restrict__ lin0b,
    const float* __restrict__ act0a, const float* __restrict__ act0b,
    const float* __restrict__ linsb, const float* __restrict__ actsa,
    const float* __restrict__ actsb, const float* __restrict__ outb) {
    extern __shared__ __align__(16) ull sm[];
    ull* bufA = sm;            // [pp*512 + i*8 + b]
    ull* bufB = sm + 1024;
    ull* wbuf = sm + 2048;     // 2 x 10240 (weights; also reduction scratch)

    const int t = threadIdx.x;
    const int o = t & 63;
    const int pp = (t >> 6) & 1;
    const int h = t >> 7;      // 0..3
    const float sig = rps[0];
    const float inv2s2 = 1.0f / (2.0f * sig * sig);

    // phase 0: x[pp][33][8] packed pairs into bufA
    for (int idx = t; idx < 2 * 264; idx += 512) {
        int q = idx / 264; int r = idx - q * 264; int i = r >> 3; int b = r & 7;
        int n0 = blockIdx.x * 4 + q * 2;
        float v0, v1;
        if (i == 0) {
            int na = n0 > 342 ? 342 : n0;
            int nb = n0 + 1 > 342 ? 342 : n0 + 1;
            int a0 = na / 49, rr = na - a0 * 49, a1 = rr / 7, a2 = rr - a1 * 7;
            float p0 = a0 - 3.0f, p1 = a1 - 3.0f, p2 = a2 - 3.0f;
            float qq = p0 * p0 + p1 * p1 + p2 * p2;
            v0 = (b == 0) ? expf(-qq * inv2s2) : (b == 1) ? p0 : (b == 2) ? p1 : (b == 3) ? p2 : 0.0f;
            a0 = nb / 49; rr = nb - a0 * 49; a1 = rr / 7; a2 = rr - a1 * 7;
            p0 = a0 - 3.0f; p1 = a1 - 3.0f; p2 = a2 - 3.0f;
            qq = p0 * p0 + p1 * p1 + p2 * p2;
            v1 = (b == 0) ? expf(-qq * inv2s2) : (b == 1) ? p0 : (b == 2) ? p1 : (b == 3) ? p2 : 0.0f;
        } else {
            v0 = cond[(i - 1) * 8 + b];
            v1 = v0;
        }
        bufA[q * 512 + i * 8 + b] = pk2(v0, v1);
    }
    __syncthreads();

    {
        const int l0s[5] = {0, 9, 17, 25, 33};
        lin2_split(g_l0, lin0b, act0a, act0b, bufA + pp * 512, bufB + pp * 512 + o * 8,
                   o, h, l0s[h], l0s[h + 1], wbuf);
    }
    gp2_split(g_gw, bufB + pp * 512, bufA + pp * 512 + o * 8, o, h, wbuf);

    for (int l = 0; l < 3; l++) {
        lin2_split(g_lw + l * 16384, linsb + l * 64, actsa + l * 256, actsb + l * 256,
                   bufA + pp * 512, bufB + pp * 512 + o * 8, o, h, h * 16, h * 16 + 16, wbuf);
        gp2_split(g_gw + (l + 1) * 81920, bufB + pp * 512, bufA + pp * 512 + o * 8, o, h, wbuf);
    }

    // out linear (packed): quarters split the 16 oi-reps 4/4/4/4; no reduction.
    const int n0 = blockIdx.x * 4 + pp * 2;          // even; n0+1 may be 343 (scratch pad)
    const ull* hbuf = bufA + pp * 512;
    for (int r = 0; r < 4; r++) {
        int oi = (h * 4 + r) * 64 + o;
        ull acc[8];
#pragma unroll
        for (int b = 0; b < 8; b++) acc[b] = 0ULL;
        for (int c = 0; c < 64; c++) {
            ull w0 = dup2(g_ow[(c * 4 + 0) * 1024 + oi]);
            ull w1 = dup2(g_ow[(c * 4 + 1) * 1024 + oi]);
            ull w2 = dup2(g_ow[(c * 4 + 2) * 1024 + oi]);
            ull w3 = dup2(g_ow[(c * 4 + 3) * 1024 + oi]);
            const ull* x8 = hbuf + c * 8;
            acc[0] = fma2(w0, x8[0], acc[0]);
            acc[1] = fma2(w1, x8[1], acc[1]);
            acc[2] = fma2(w1, x8[2], acc[2]);
            acc[3] = fma2(w1, x8[3], acc[3]);
            acc[4] = fma2(w2, x8[4], acc[4]);
            acc[5] = fma2(w2, x8[5], acc[5]);
            acc[6] = fma2(w2, x8[6], acc[6]);
            acc[7] = fma2(w3, x8[7], acc[7]);
        }
        float bv = outb[oi];
        acc[0] = add2(acc[0], pk2(bv, bv));
#pragma unroll
        for (int b = 0; b < 8; b++)
            *(ull*)&g_kf[oi * 2752 + b * 344 + n0] = acc[b];
    }
}

// ---------------------------------------------------------------------------
// k_expand: one block per (o,i). shell*FACTOR in smem, then 64 gathered
// coalesced store rows: K[o,l,i,m,n] = kshell[n,k*(l,m)] * cw[o,i,pid]*sign.
// ---------------------------------------------------------------------------
__global__ void __launch_bounds__(128) k_expand(
    const float* __restrict__ cw, const float* __restrict__ ss, float* __restrict__ out) {
    __shared__ float s_ks[8 * 344];
    __shared__ float s_q[344];
    __shared__ float s_cf[64];
    __shared__ int   s_ki[64];

    const int t = threadIdx.x;
    const int oi = blockIdx.x;
    const int o = oi >> 5, i = oi & 31;

    for (int n = t; n < 343; n += 128) {
        int a0 = n / 49; int rr = n - a0 * 49; int a1 = rr / 7; int a2 = rr - a1 * 7;
        float p0 = a0 - 3.0f, p1 = a1 - 3.0f, p2 = a2 - 3.0f;
        s_q[n] = p0 * p0 + p1 * p1 + p2 * p2;
    }
    if (t < 64) {
        int l = t >> 3, m = t & 7;
        int km = c_mask[l] ^ c_mask[m];
        int k = c_inv[km];
        int s = 0;
#pragma unroll
        for (int bi = 0; bi < 3; bi++)
            if (c_mask[m] & (1 << bi)) s += __popc((unsigned)(km >> (bi + 1)));
        float sgn = (s & 1) ? -1.0f : 1.0f;
        int pv = pid_rt(c_gr[k], c_gr[l], c_gr[m]);
        s_cf[t] = cw[oi * 20 + pv] * sgn;
        s_ki[t] = k;
    }
    __syncthreads();

#pragma unroll
    for (int b = 0; b < 8; b++) {
        float sg = ss[oi * 8 + b];
        float is2 = 1.0f / (sg * sg);
        for (int n = t; n < 343; n += 128)
            s_ks[b * 344 + n] = g_kf[oi * 2752 + b * 344 + n] * expf(-s_q[n] * is2) * FACTOR_;
    }
    __syncthreads();

    for (int lm = 0; lm < 64; lm++) {
        int ks = s_ki[lm];
        float cf = s_cf[lm];
        int l = lm >> 3, m = lm & 7;
        long base = (long)(((o * 8 + l) * 32 + i) * 8 + m) * 343;
        for (int n = t; n < 343; n += 128)
            out[base + n] = s_ks[ks * 344 + n] * cf;
    }
}

// ---------------------------------------------------------------------------
extern "C" void kernel_launch(void* const* d_in, const int* in_sizes, int n_in,
                              void* d_out, int out_size) {
    const float* cond = (const float*)d_in[0];
    const float* rps  = (const float*)d_in[1];
    const float* cw   = (const float*)d_in[2];
    const float* l0W  = (const float*)d_in[3];
    const float* l0b  = (const float*)d_in[4];
    const float* a0a  = (const float*)d_in[5];
    const float* a0b  = (const float*)d_in[6];
    const float* gpsw = (const float*)d_in[7];
    const float* lW   = (const float*)d_in[8];
    const float* lb   = (const float*)d_in[9];
    const float* aa   = (const float*)d_in[10];
    const float* ab   = (const float*)d_in[11];
    const float* oW   = (const float*)d_in[12];
    const float* ob   = (const float*)d_in[13];
    const float* ss   = (const float*)d_in[14];
    float* out = (float*)d_out;

    cudaFuncSetAttribute(k_mlp, cudaFuncAttributeMaxDynamicSharedMemorySize, 180224);

    k_prep<<<2529, 256>>>(gpsw, lW, l0W, oW);
    k_mlp<<<86, 512, 180224>>>(cond, rps, l0b, a0a, a0b, lb, aa, ab, ob);
    k_expand<<<1024, 128>>>(cw, ss, out);
}

// round 17
// speedup vs baseline: 3.2017x; 1.0617x over previous
#include <cuda_runtime.h>
#include <cuda_bf16.h>
#include <math.h>

// ---------------------------------------------------------------------------
// DIM=3 Euclidean GA. 8 blades (order: (),e0,e1,e2,e01,e02,e12,e012),
// grades {0,1,1,1,2,2,2,3}. KERNEL_SIZE=7 -> 343 pts. C_IN=C_OUT=32, H=64,
// 4 layers, P=20 paths. Output (256,256,7,7,7) fp32.
// ---------------------------------------------------------------------------
typedef unsigned long long ull;
#define FACTOR_ 0.05399492471f   // 1/sqrt(343)

// -------- device scratch (no allocations allowed); plain float weights ------
__device__ __align__(16) float g_gw[4 * 64 * 20 * 64];   // gps_w  -> [l][i][p][o]
__device__ __align__(16) float g_lw[3 * 64 * 4 * 64];    // lins_W -> [l][i][g][o]
__device__ __align__(16) float g_l0[33 * 4 * 64];        // lin0_W -> [i][g][o]
__device__ __align__(16) float g_ow[64 * 4 * 1024];      // out_W  -> [c][g][oi]
__device__ __align__(16) ull   g_h[176 * 512];           // hidden pairs [pr][c][b] (pad 172->176)
__device__ __align__(16) float g_kf[1024 * 8 * 344];     // kfield [oi][b][n] (n-stride 344)

__constant__ int c_mask[8] = {0, 1, 2, 4, 3, 5, 6, 7};
__constant__ int c_inv[8]  = {0, 1, 2, 4, 3, 5, 6, 7};
__constant__ int c_gr[8]   = {0, 1, 1, 1, 2, 2, 2, 3};

// -------- f32x2 packed helpers --------
__device__ __forceinline__ ull pk2(float a, float b) {
    ull r; asm("mov.b64 %0, {%1,%2};" : "=l"(r) : "f"(a), "f"(b)); return r;
}
__device__ __forceinline__ ull dup2(float a) {          // (w,w)
    ull r; asm("mov.b64 %0, {%1,%1};" : "=l"(r) : "f"(a)); return r;
}
__device__ __forceinline__ void upk2(ull v, float& a, float& b) {
    asm("mov.b64 {%0,%1}, %2;" : "=f"(a), "=f"(b) : "l"(v));
}
__device__ __forceinline__ ull fma2(ull a, ull b, ull c) {
    ull d; asm("fma.rn.f32x2 %0, %1, %2, %3;" : "=l"(d) : "l"(a), "l"(b), "l"(c)); return d;
}
__device__ __forceinline__ ull mul2(ull a, ull b) {
    ull d; asm("mul.rn.f32x2 %0, %1, %2;" : "=l"(d) : "l"(a), "l"(b)); return d;
}
__device__ __forceinline__ ull add2(ull a, ull b) {
    ull d; asm("add.rn.f32x2 %0, %1, %2;" : "=l"(d) : "l"(a), "l"(b)); return d;
}
#define POS8TH 0x3E0000003E000000ULL   // {0.125f, 0.125f}
#define NEG8TH 0xBE000000BE000000ULL   // {-0.125f,-0.125f}

// -------- compile-time tables for the gp layers --------
struct Tables {
    int   pid[4][4][4];
    int   pairM[8][8];
    float pairSign[8][8];
    int   pairPid[8][8];
};
__host__ __device__ constexpr int popc_(int x) {
    return (x & 1) + ((x >> 1) & 1) + ((x >> 2) & 1);
}
__host__ __device__ constexpr int signOf_(int a, int b) {
    int s = 0;
    for (int i = 0; i < 3; i++)
        if (b & (1 << i)) s += popc_(a >> (i + 1));
    return (s & 1) ? -1 : 1;
}
__host__ __device__ constexpr Tables buildTables() {
    Tables T{};
    constexpr int MSK[8] = {0, 1, 2, 4, 3, 5, 6, 7};
    constexpr int GRD[8] = {0, 1, 1, 1, 2, 2, 2, 3};
    int p = 0;
    for (int a = 0; a < 4; a++)
        for (int b = 0; b < 4; b++)
            for (int c = 0; c < 4; c++) {
                bool v = false;
                for (int t = 0; t <= 3; t++)
                    if (t <= a && t <= c && a + c - t <= 3 && a + c - 2 * t == b) v = true;
                T.pid[a][b][c] = v ? p++ : -1;
            }
    for (int j = 0; j < 8; j++)
        for (int k = 0; k < 8; k++) {
            int mm = MSK[k] ^ MSK[j];
            int m = 0;
            for (int q = 0; q < 8; q++)
                if (MSK[q] == mm) m = q;
            T.pairM[j][k] = m;
            T.pairSign[j][k] = (float)signOf_(MSK[k], mm);
            T.pairPid[j][k] = T.pid[GRD[k]][GRD[j]][GRD[m]];
        }
    return T;
}
__device__ int pid_rt(int a, int b, int c) {
    int p = 0;
    for (int aa = 0; aa < 4; aa++)
        for (int bb = 0; bb < 4; bb++)
            for (int cc = 0; cc < 4; cc++) {
                bool v = false;
                for (int t = 0; t <= 3; t++)
                    if (t <= aa && t <= cc && aa + cc - t <= 3 && aa + cc - 2 * t == bb) v = true;
                if (aa == a && bb == b && cc == c) return v ? p : 0;
                if (v) p++;
            }
    return 0;
}

// ---------------------------------------------------------------------------
// prep: transpose weights (o-last), plain float
// ---------------------------------------------------------------------------
__global__ void k_prep(const float* __restrict__ gps_w, const float* __restrict__ lins_W,
                       const float* __restrict__ lin0_W, const float* __restrict__ out_W) {
    const int N1 = 327680, N2 = 49152, N3 = 8448, N4 = 262144;
    int idx = blockIdx.x * blockDim.x + threadIdx.x;
    if (idx < N1) {
        int o = idx & 63; int r = idx >> 6; int p = r % 20; r /= 20;
        int i = r & 63; int l = r >> 6;
        g_gw[idx] = gps_w[((l * 64 + o) * 64 + i) * 20 + p];
    } else if (idx < N1 + N2) {
        int j = idx - N1; int o = j & 63; int r = j >> 6; int g = r & 3; r >>= 2;
        int i = r & 63; int l = r >> 6;
        g_lw[j] = lins_W[((l * 4 + g) * 64 + o) * 64 + i];
    } else if (idx < N1 + N2 + N3) {
        int j = idx - N1 - N2; int o = j & 63; int r = j >> 6; int g = r & 3; int i = r >> 2;
        g_l0[j] = lin0_W[(g * 64 + o) * 33 + i];
    } else if (idx < N1 + N2 + N3 + N4) {
        int j = idx - N1 - N2 - N3; int oi = j & 1023; int r = j >> 10; int g = r & 3; int c = r >> 2;
        g_ow[j] = out_W[(g * 1024 + oi) * 64 + c];
    }
}

// ---------------------------------------------------------------------------
// cp.async chunk copy: 81,920 B contiguous, 512 threads
// ---------------------------------------------------------------------------
__device__ __forceinline__ void copy_chunk(void* dst, const void* src) {
    unsigned s = (unsigned)__cvta_generic_to_shared(dst);
    const char* g = (const char*)src;
    int t = threadIdx.x;
#pragma unroll
    for (int j = 0; j < 10; j++) {
        asm volatile("cp.async.ca.shared.global [%0], [%1], 16;"
                     :: "r"(s + (t + j * 512) * 16), "l"(g + (t + j * 512) * 16));
    }
    asm volatile("cp.async.commit_group;" ::: "memory");
}

// ---------------------------------------------------------------------------
// split linear + silu: quarters split i-range, reduce via smem, h==0 silu.
// ---------------------------------------------------------------------------
__device__ __forceinline__ void lin2_split(
    const float* __restrict__ lwf, const float* __restrict__ bias,
    const float* __restrict__ aa, const float* __restrict__ ab,
    const ull* __restrict__ xin, ull* __restrict__ yout,
    int o, int h, int i0, int i1, ull* __restrict__ red) {
    ull acc[8];
#pragma unroll
    for (int b = 0; b < 8; b++) acc[b] = 0ULL;
    for (int i = i0; i < i1; i++) {
        ull w0 = dup2(lwf[(i * 4 + 0) * 64 + o]);
        ull w1 = dup2(lwf[(i * 4 + 1) * 64 + o]);
        ull w2 = dup2(lwf[(i * 4 + 2) * 64 + o]);
        ull w3 = dup2(lwf[(i * 4 + 3) * 64 + o]);
        const ull* x8 = xin + i * 8;
        acc[0] = fma2(w0, x8[0], acc[0]);
        acc[1] = fma2(w1, x8[1], acc[1]);
        acc[2] = fma2(w1, x8[2], acc[2]);
        acc[3] = fma2(w1, x8[3], acc[3]);
        acc[4] = fma2(w2, x8[4], acc[4]);
        acc[5] = fma2(w2, x8[5], acc[5]);
        acc[6] = fma2(w2, x8[6], acc[6]);
        acc[7] = fma2(w3, x8[7], acc[7]);
    }
    const int t = threadIdx.x;
    if (h > 0) {
#pragma unroll
        for (int b = 0; b < 8; b++) red[(t - 128) * 9 + b] = acc[b];
    }
    __syncthreads();
    if (h == 0) {
#pragma unroll
        for (int b = 0; b < 8; b++) {
            acc[b] = add2(acc[b], red[t * 9 + b]);
            acc[b] = add2(acc[b], red[(t + 128) * 9 + b]);
            acc[b] = add2(acc[b], red[(t + 256) * 9 + b]);
        }
        float bl = bias[o];
        acc[0] = add2(acc[0], pk2(bl, bl));
        float lo[8], hi[8];
#pragma unroll
        for (int b = 0; b < 8; b++) upk2(acc[b], lo[b], hi[b]);
        float q0l = lo[0] * lo[0];
        float q1l = lo[1] * lo[1] + lo[2] * lo[2] + lo[3] * lo[3];
        float q2l = lo[4] * lo[4] + lo[5] * lo[5] + lo[6] * lo[6];
        float q3l = lo[7] * lo[7];
        float q0h = hi[0] * hi[0];
        float q1h = hi[1] * hi[1] + hi[2] * hi[2] + hi[3] * hi[3];
        float q2h = hi[4] * hi[4] + hi[5] * hi[5] + hi[6] * hi[6];
        float q3h = hi[7] * hi[7];
        float a0 = aa[o * 4 + 0], a1 = aa[o * 4 + 1], a2 = aa[o * 4 + 2], a3 = aa[o * 4 + 3];
        float b0 = ab[o * 4 + 0], b1 = ab[o * 4 + 1], b2 = ab[o * 4 + 2], b3 = ab[o * 4 + 3];
        float g0l = 1.0f / (1.0f + expf(-(a0 * q0l + b0)));
        float g1l = 1.0f / (1.0f + expf(-(a1 * q1l + b1)));
        float g2l = 1.0f / (1.0f + expf(-(a2 * q2l + b2)));
        float g3l = 1.0f / (1.0f + expf(-(a3 * q3l + b3)));
        float g0h = 1.0f / (1.0f + expf(-(a0 * q0h + b0)));
        float g1h = 1.0f / (1.0f + expf(-(a1 * q1h + b1)));
        float g2h = 1.0f / (1.0f + expf(-(a2 * q2h + b2)));
        float g3h = 1.0f / (1.0f + expf(-(a3 * q3h + b3)));
        yout[0] = pk2(lo[0] * g0l, hi[0] * g0h);
        yout[1] = pk2(lo[1] * g1l, hi[1] * g1h);
        yout[2] = pk2(lo[2] * g1l, hi[2] * g1h);
        yout[3] = pk2(lo[3] * g1l, hi[3] * g1h);
        yout[4] = pk2(lo[4] * g2l, hi[4] * g2h);
        yout[5] = pk2(lo[5] * g2l, hi[5] * g2h);
        yout[6] = pk2(lo[6] * g2l, hi[6] * g2h);
        yout[7] = pk2(lo[7] * g3l, hi[7] * g3h);
    }
    __syncthreads();
}

// ---------------------------------------------------------------------------
// split gp layer: 4 staged chunks of 16 i's (80 KB floats each, double-buffer);
// quarter h handles ii = 4h..4h+3 within each chunk; 4-way smem reduce.
// ---------------------------------------------------------------------------
__device__ __forceinline__ void gp2_split(const float* __restrict__ gwf, const ull* __restrict__ xin,
                                          ull* __restrict__ yout, int o, int h,
                                          ull* __restrict__ wbuf) {
    constexpr Tables T = buildTables();
    ull accP[8], accN[8];
#pragma unroll
    for (int j = 0; j < 8; j++) { accP[j] = 0ULL; accN[j] = 0ULL; }

    copy_chunk(wbuf, gwf);   // chunk 0 (i = 0..15)
    for (int c = 0; c < 4; c++) {
        if (c < 3) copy_chunk(wbuf + ((c + 1) & 1) * 10240, gwf + (c + 1) * 20480);
        if (c < 3) asm volatile("cp.async.wait_group 1;" ::: "memory");
        else       asm volatile("cp.async.wait_group 0;" ::: "memory");
        __syncthreads();
        const float* wf = (const float*)(wbuf + (c & 1) * 10240);
#pragma unroll
        for (int q = 0; q < 4; q++) {
            const int ii = h * 4 + q;
            ull wp[20];
#pragma unroll
            for (int p = 0; p < 20; p++) wp[p] = dup2(wf[(ii * 20 + p) * 64 + o]);
            const ull* x8 = xin + (c * 16 + ii) * 8;
            ull t8[8];
#pragma unroll
            for (int b = 0; b < 8; b++) t8[b] = x8[b];
#pragma unroll
            for (int j = 0; j < 8; j++) {
                ull prod[8];
#pragma unroll
                for (int k = 0; k < 8; k++) {
                    int m = T.pairM[j][k];
                    if (k <= m) prod[k] = mul2(t8[k], t8[m]);
                }
#pragma unroll
                for (int k = 0; k < 8; k++) {
                    int m = T.pairM[j][k];
                    ull pr = (k <= m) ? prod[k] : prod[m];
                    if (T.pairSign[j][k] > 0.0f)
                        accP[j] = fma2(wp[T.pairPid[j][k]], pr, accP[j]);
                    else
                        accN[j] = fma2(wp[T.pairPid[j][k]], pr, accN[j]);
                }
            }
        }
        __syncthreads();
    }
    ull part[8];
#pragma unroll
    for (int j = 0; j < 8; j++)
        part[j] = fma2(accN[j], (ull)NEG8TH, mul2(accP[j], (ull)POS8TH));
    const int t = threadIdx.x;
    if (h > 0) {
#pragma unroll
        for (int j = 0; j < 8; j++) wbuf[(t - 128) * 9 + j] = part[j];
    }
    __syncthreads();
    if (h == 0) {
#pragma unroll
        for (int j = 0; j < 8; j++) {
            part[j] = add2(part[j], wbuf[t * 9 + j]);
            part[j] = add2(part[j], wbuf[(t + 128) * 9 + j]);
            yout[j] = add2(part[j], wbuf[(t + 256) * 9 + j]);
        }
    }
    __syncthreads();
}

// ---------------------------------------------------------------------------
// k_mlp: 86 blocks x 512 threads; ends at 4th gp layer, dumps h to g_h.
// dyn smem: bufA[1024] | bufB[1024] | wbuf[2*10240] ull = 180224 B
// ---------------------------------------------------------------------------
__global__ void __launch_bounds__(512) k_mlp(
    const float* __restrict__ cond, const float* __restrict__ rps,
    const float* __restrict__ lin0b,
    const float* __restrict__ act0a, const float* __restrict__ act0b,
    const float* __restrict__ linsb, const float* __restrict__ actsa,
    const float* __restrict__ actsb) {
    extern __shared__ __align__(16) ull sm[];
    ull* bufA = sm;            // [pp*512 + i*8 + b]
    ull* bufB = sm + 1024;
    ull* wbuf = sm + 2048;     // 2 x 10240 (weights; also reduction scratch)

    const int t = threadIdx.x;
    const int o = t & 63;
    const int pp = (t >> 6) & 1;
    const int h = t >> 7;      // 0..3
    const float sig = rps[0];
    const float inv2s2 = 1.0f / (2.0f * sig * sig);

    // phase 0: x[pp][33][8] packed pairs into bufA
    for (int idx = t; idx < 2 * 264; idx += 512) {
        int q = idx / 264; int r = idx - q * 264; int i = r >> 3; int b = r & 7;
        int n0 = blockIdx.x * 4 + q * 2;
        float v0, v1;
        if (i == 0) {
            int na = n0 > 342 ? 342 : n0;
            int nb = n0 + 1 > 342 ? 342 : n0 + 1;
            int a0 = na / 49, rr = na - a0 * 49, a1 = rr / 7, a2 = rr - a1 * 7;
            float p0 = a0 - 3.0f, p1 = a1 - 3.0f, p2 = a2 - 3.0f;
            float qq = p0 * p0 + p1 * p1 + p2 * p2;
            v0 = (b == 0) ? expf(-qq * inv2s2) : (b == 1) ? p0 : (b == 2) ? p1 : (b == 3) ? p2 : 0.0f;
            a0 = nb / 49; rr = nb - a0 * 49; a1 = rr / 7; a2 = rr - a1 * 7;
            p0 = a0 - 3.0f; p1 = a1 - 3.0f; p2 = a2 - 3.0f;
            qq = p0 * p0 + p1 * p1 + p2 * p2;
            v1 = (b == 0) ? expf(-qq * inv2s2) : (b == 1) ? p0 : (b == 2) ? p1 : (b == 3) ? p2 : 0.0f;
        } else {
            v0 = cond[(i - 1) * 8 + b];
            v1 = v0;
        }
        bufA[q * 512 + i * 8 + b] = pk2(v0, v1);
    }
    __syncthreads();

    {
        const int l0s[5] = {0, 9, 17, 25, 33};
        lin2_split(g_l0, lin0b, act0a, act0b, bufA + pp * 512, bufB + pp * 512 + o * 8,
                   o, h, l0s[h], l0s[h + 1], wbuf);
    }
    gp2_split(g_gw, bufB + pp * 512, bufA + pp * 512 + o * 8, o, h, wbuf);

    for (int l = 0; l < 3; l++) {
        lin2_split(g_lw + l * 16384, linsb + l * 64, actsa + l * 256, actsb + l * 256,
                   bufA + pp * 512, bufB + pp * 512 + o * 8, o, h, h * 16, h * 16 + 16, wbuf);
        gp2_split(g_gw + (l + 1) * 81920, bufB + pp * 512, bufA + pp * 512 + o * 8, o, h, wbuf);
    }

    // dump hidden state: bufA[0..1023] -> g_h[blockIdx*1024 ...]
    for (int j = t; j < 1024; j += 512)
        g_h[blockIdx.x * 1024 + j] = bufA[j];
}

// ---------------------------------------------------------------------------
// k_out: out-linear as tiled GEMM. grid (16 oi-tiles, 11 pair-tiles), 256 thr.
// smem: s_h[16 pairs][512] ull (64 KB) | s_w[256 rows][64] float (64 KB)
// thread: oiL = t&63, u = t>>6; computes 4 pairs (u, u+4, u+8, u+12).
// ---------------------------------------------------------------------------
__global__ void __launch_bounds__(256) k_out(const float* __restrict__ outb) {
    extern __shared__ __align__(16) ull smo[];
    ull*   s_h = smo;                       // 8192 ull
    float* s_w = (float*)(smo + 8192);      // 16384 floats

    const int t = threadIdx.x;
    const int oi0 = blockIdx.x * 64;
    const int pr0 = blockIdx.y * 16;

    // stage h tile: 64 KB contiguous from g_h + pr0*512
    {
        unsigned s = (unsigned)__cvta_generic_to_shared(s_h);
        const char* g = (const char*)(g_h + pr0 * 512);
#pragma unroll
        for (int j = 0; j < 16; j++)
            asm volatile("cp.async.ca.shared.global [%0], [%1], 16;"
                         :: "r"(s + (t + j * 256) * 16), "l"(g + (t + j * 256) * 16));
        // stage weight slice: rows r=0..255 of 64 floats from g_ow[r*1024 + oi0]
        unsigned sw = (unsigned)__cvta_generic_to_shared(s_w);
        const char* gw = (const char*)g_ow;
#pragma unroll
        for (int j = 0; j < 16; j++) {
            int ch = t + j * 256;
            int row = ch >> 4;
            int off = (ch & 15) * 16;
            asm volatile("cp.async.ca.shared.global [%0], [%1], 16;"
                         :: "r"(sw + ch * 16), "l"(gw + row * 4096 + oi0 * 4 + off));
        }
        asm volatile("cp.async.commit_group;" ::: "memory");
        asm volatile("cp.async.wait_group 0;" ::: "memory");
        __syncthreads();
    }

    const int oiL = t & 63;
    const int u = t >> 6;
    ull acc[4][8];
#pragma unroll
    for (int v = 0; v < 4; v++)
#pragma unroll
        for (int b = 0; b < 8; b++) acc[v][b] = 0ULL;

    for (int c = 0; c < 64; c++) {
        ull w0 = dup2(s_w[(c * 4 + 0) * 64 + oiL]);
        ull w1 = dup2(s_w[(c * 4 + 1) * 64 + oiL]);
        ull w2 = dup2(s_w[(c * 4 + 2) * 64 + oiL]);
        ull w3 = dup2(s_w[(c * 4 + 3) * 64 + oiL]);
#pragma unroll
        for (int v = 0; v < 4; v++) {
            const ull* x8 = s_h + (u + 4 * v) * 512 + c * 8;
            acc[v][0] = fma2(w0, x8[0], acc[v][0]);
            acc[v][1] = fma2(w1, x8[1], acc[v][1]);
            acc[v][2] = fma2(w1, x8[2], acc[v][2]);
            acc[v][3] = fma2(w1, x8[3], acc[v][3]);
            acc[v][4] = fma2(w2, x8[4], acc[v][4]);
            acc[v][5] = fma2(w2, x8[5], acc[v][5]);
            acc[v][6] = fma2(w2, x8[6], acc[v][6]);
            acc[v][7] = fma2(w3, x8[7], acc[v][7]);
        }
    }

    const int oi = oi0 + oiL;
    float bv = outb[oi];
    ull bb = pk2(bv, bv);
#pragma unroll
    for (int v = 0; v < 4; v++) {
        int pr = pr0 + u + 4 * v;
        if (pr < 172) {
            acc[v][0] = add2(acc[v][0], bb);
            int n0 = pr * 2;
#pragma unroll
            for (int b = 0; b < 8; b++)
                *(ull*)&g_kf[oi * 2752 + b * 344 + n0] = acc[v][b];
        }
    }
}

// ---------------------------------------------------------------------------
// k_expand: one block per (o,i). shell*FACTOR in smem, then 64 gathered
// coalesced store rows: K[o,l,i,m,n] = kshell[n,k*(l,m)] * cw[o,i,pid]*sign.
// ---------------------------------------------------------------------------
__global__ void __launch_bounds__(128) k_expand(
    const float* __restrict__ cw, const float* __restrict__ ss, float* __restrict__ out) {
    __shared__ float s_ks[8 * 344];
    __shared__ float s_q[344];
    __shared__ float s_cf[64];
    __shared__ int   s_ki[64];

    const int t = threadIdx.x;
    const int oi = blockIdx.x;
    const int o = oi >> 5, i = oi & 31;

    for (int n = t; n < 343; n += 128) {
        int a0 = n / 49; int rr = n - a0 * 49; int a1 = rr / 7; int a2 = rr - a1 * 7;
        float p0 = a0 - 3.0f, p1 = a1 - 3.0f, p2 = a2 - 3.0f;
        s_q[n] = p0 * p0 + p1 * p1 + p2 * p2;
    }
    if (t < 64) {
        int l = t >> 3, m = t & 7;
        int km = c_mask[l] ^ c_mask[m];
        int k = c_inv[km];
        int s = 0;
#pragma unroll
        for (int bi = 0; bi < 3; bi++)
            if (c_mask[m] & (1 << bi)) s += __popc((unsigned)(km >> (bi + 1)));
        float sgn = (s & 1) ? -1.0f : 1.0f;
        int pv = pid_rt(c_gr[k], c_gr[l], c_gr[m]);
        s_cf[t] = cw[oi * 20 + pv] * sgn;
        s_ki[t] = k;
    }
    __syncthreads();

#pragma unroll
    for (int b = 0; b < 8; b++) {
        float sg = ss[oi * 8 + b];
        float is2 = 1.0f / (sg * sg);
        for (int n = t; n < 343; n += 128)
            s_ks[b * 344 + n] = g_kf[oi * 2752 + b * 344 + n] * expf(-s_q[n] * is2) * FACTOR_;
    }
    __syncthreads();

    for (int lm = 0; lm < 64; lm++) {
        int ks = s_ki[lm];
        float cf = s_cf[lm];
        int l = lm >> 3, m = lm & 7;
        long base = (long)(((o * 8 + l) * 32 + i) * 8 + m) * 343;
        for (int n = t; n < 343; n += 128)
            out[base + n] = s_ks[ks * 344 + n] * cf;
    }
}

// ---------------------------------------------------------------------------
extern "C" void kernel_launch(void* const* d_in, const int* in_sizes, int n_in,
                              void* d_out, int out_size) {
    const float* cond = (const float*)d_in[0];
    const float* rps  = (const float*)d_in[1];
    const float* cw   = (const float*)d_in[2];
    const float* l0W  = (const float*)d_in[3];
    const float* l0b  = (const float*)d_in[4];
    const float* a0a  = (const float*)d_in[5];
    const float* a0b  = (const float*)d_in[6];
    const float* gpsw = (const float*)d_in[7];
    const float* lW   = (const float*)d_in[8];
    const float* lb   = (const float*)d_in[9];
    const float* aa   = (const float*)d_in[10];
    const float* ab   = (const float*)d_in[11];
    const float* oW   = (const float*)d_in[12];
    const float* ob   = (const float*)d_in[13];
    const float* ss   = (const float*)d_in[14];
    float* out = (float*)d_out;

    cudaFuncSetAttribute(k_mlp, cudaFuncAttributeMaxDynamicSharedMemorySize, 180224);
    cudaFuncSetAttribute(k_out, cudaFuncAttributeMaxDynamicSharedMemorySize, 131072);

    k_prep<<<2529, 256>>>(gpsw, lW, l0W, oW);
    k_mlp<<<86, 512, 180224>>>(cond, rps, l0b, a0a, a0b, lb, aa, ab);
    k_out<<<dim3(16, 11), 256, 131072>>>(ob);
    k_expand<<<1024, 128>>>(cw, ss, out);
}